// round 7
// baseline (speedup 1.0000x reference)
#include <cuda_runtime.h>

#define S_PER_BLK 4
#define T_STEPS   1024
#define H_DIM     64
#define G_DIM     256   // 4*H
#define D_DIM     4
#define NTHREADS  384   // 128 L0 threads (2 rows each) + 256 L1 threads (1 row)
#define L0_SZ     128
#define L1_SZ     256
#define RING_D    4

// named barrier ids
#define BAR_L0INT  1
#define BAR_L1INT  2
#define BAR_READY  3   // 3,4,5,6 (phase p -> 3+p)
#define BAR_FREE   7   // 7,8,9,10

typedef unsigned long long ull;

__device__ __forceinline__ void bar_sync(int id, int cnt) {
    asm volatile("bar.sync %0, %1;" :: "r"(id), "r"(cnt) : "memory");
}
__device__ __forceinline__ void bar_arrive(int id, int cnt) {
    asm volatile("bar.arrive %0, %1;" :: "r"(id), "r"(cnt) : "memory");
}

// ---- fast activations ----
__device__ __forceinline__ float fsig(float x) {
    float e = __expf(-x);
    float d = 1.0f + e;
    float r;
    asm("rcp.approx.f32 %0, %1;" : "=f"(r) : "f"(d));
    return r;
}
__device__ __forceinline__ float ftanh(float x) {
    return __fmaf_rn(2.0f, fsig(2.0f * x), -1.0f);
}

// ---- packed f32x2 fma (sm_100+) ----
__device__ __forceinline__ void fma2(ull& d, ull a, ull b, ull c) {
    asm("fma.rn.f32x2 %0, %1, %2, %3;" : "=l"(d) : "l"(a), "l"(b), "l"(c));
}
__device__ __forceinline__ float fold2(ull a) {
    float lo, hi;
    asm("mov.b64 {%0,%1}, %2;" : "=f"(lo), "=f"(hi) : "l"(a));
    return lo + hi;
}
__device__ __forceinline__ ull f4lo(const float4& v) {
    ull r; asm("mov.b64 %0, {%1,%2};" : "=l"(r) : "f"(v.x), "f"(v.y)); return r;
}
__device__ __forceinline__ ull f4hi(const float4& v) {
    ull r; asm("mov.b64 %0, {%1,%2};" : "=l"(r) : "f"(v.z), "f"(v.w)); return r;
}

// smem layout (floats):
//   xs   : S*T*D        = 16384
//   ring : RING_D*S*H   = 1024   (h1 ring, L0 -> L1; reused as classifier scratch)
//   h2s  : S*H          = 256
// total 17664 floats = 70656 bytes

__global__ __launch_bounds__(NTHREADS, 1)
void lstm_fused_kernel(const float* __restrict__ x,
                       const float* __restrict__ W_ih0,
                       const float* __restrict__ W_hh0,
                       const float* __restrict__ b0,
                       const float* __restrict__ W_ih1,
                       const float* __restrict__ W_hh1,
                       const float* __restrict__ b1,
                       const float* __restrict__ W_fc1,
                       const float* __restrict__ b_fc1,
                       const float* __restrict__ W_fc2,
                       const float* __restrict__ b_fc2,
                       float* __restrict__ out)
{
    extern __shared__ float sm[];
    float* xs   = sm;                                   // [S][T][D]
    float* ring = sm + S_PER_BLK * T_STEPS * D_DIM;     // [RING_D][S][H]
    float* h2s  = ring + RING_D * S_PER_BLK * H_DIM;    // [S][H]

    const int tid  = threadIdx.x;
    const bool isL0 = tid < L0_SZ;
    const int bb   = blockIdx.x * S_PER_BLK;

    // ---- common staging ----
    {
        const float4* gx = (const float4*)(x + (size_t)bb * T_STEPS * D_DIM);
        float4*       sx = (float4*)xs;
        #pragma unroll 4
        for (int i = tid; i < S_PER_BLK * T_STEPS; i += NTHREADS) sx[i] = gx[i];
    }
    for (int i = tid; i < RING_D * S_PER_BLK * H_DIM; i += NTHREADS) ring[i] = 0.f;
    for (int i = tid; i < S_PER_BLK * H_DIM; i += NTHREADS) h2s[i] = 0.f;

    __syncthreads();

    if (isL0) {
        // ========== L0: 128 threads. thread = (h = tid>>1, parity = tid&1) ==========
        // parity 0 -> rows h (i-gate), h+128 (g-gate)
        // parity 1 -> rows h+64 (f),   h+192 (o)
        const int h      = tid >> 1;
        const int parity = tid & 1;
        const int rowA   = h + parity * 64;
        const int rowB   = rowA + 128;

        float4 w0a[16], w0b[16];
        {
            const float4* pa = (const float4*)(W_hh0 + rowA * H_DIM);
            const float4* pb = (const float4*)(W_hh0 + rowB * H_DIM);
            #pragma unroll
            for (int i = 0; i < 16; i++) { w0a[i] = pa[i]; w0b[i] = pb[i]; }
        }
        float wiA[D_DIM], wiB[D_DIM];
        #pragma unroll
        for (int d = 0; d < D_DIM; d++) {
            wiA[d] = W_ih0[rowA * D_DIM + d];
            wiB[d] = W_ih0[rowB * D_DIM + d];
        }
        const float biasA = b0[rowA];
        const float biasB = b0[rowB];

        // even lane updates samples 0,1 ; odd lane samples 2,3
        float c1a = 0.f, c1b = 0.f;

        for (int t = 0; t < T_STEPS; t++) {
            const int p = t & 3;
            if (t >= RING_D) bar_sync(BAR_FREE + p, NTHREADS);

            const float4* h1p = (const float4*)(ring + ((t - 1) & 3) * S_PER_BLK * H_DIM);

            float actA[S_PER_BLK], actB[S_PER_BLK];
            #pragma unroll
            for (int half = 0; half < 2; half++) {
                const int s0 = 2 * half, s1 = s0 + 1;
                ull aA0 = 0, aA1 = 0, aB0 = 0, aB1 = 0;
                #pragma unroll
                for (int k = 0; k < 16; k++) {
                    const float4 hv0 = h1p[s0 * 16 + k];
                    const float4 hv1 = h1p[s1 * 16 + k];
                    fma2(aA0, f4lo(w0a[k]), f4lo(hv0), aA0);
                    fma2(aA0, f4hi(w0a[k]), f4hi(hv0), aA0);
                    fma2(aA1, f4lo(w0a[k]), f4lo(hv1), aA1);
                    fma2(aA1, f4hi(w0a[k]), f4hi(hv1), aA1);
                    fma2(aB0, f4lo(w0b[k]), f4lo(hv0), aB0);
                    fma2(aB0, f4hi(w0b[k]), f4hi(hv0), aB0);
                    fma2(aB1, f4lo(w0b[k]), f4lo(hv1), aB1);
                    fma2(aB1, f4hi(w0b[k]), f4hi(hv1), aB1);
                }
                const float4 xv0 = ((const float4*)xs)[s0 * T_STEPS + t];
                const float4 xv1 = ((const float4*)xs)[s1 * T_STEPS + t];

                float pA0 = fold2(aA0) + biasA;
                pA0 = __fmaf_rn(xv0.x, wiA[0], pA0);
                pA0 = __fmaf_rn(xv0.y, wiA[1], pA0);
                pA0 = __fmaf_rn(xv0.z, wiA[2], pA0);
                pA0 = __fmaf_rn(xv0.w, wiA[3], pA0);
                float pA1 = fold2(aA1) + biasA;
                pA1 = __fmaf_rn(xv1.x, wiA[0], pA1);
                pA1 = __fmaf_rn(xv1.y, wiA[1], pA1);
                pA1 = __fmaf_rn(xv1.z, wiA[2], pA1);
                pA1 = __fmaf_rn(xv1.w, wiA[3], pA1);
                float pB0 = fold2(aB0) + biasB;
                pB0 = __fmaf_rn(xv0.x, wiB[0], pB0);
                pB0 = __fmaf_rn(xv0.y, wiB[1], pB0);
                pB0 = __fmaf_rn(xv0.z, wiB[2], pB0);
                pB0 = __fmaf_rn(xv0.w, wiB[3], pB0);
                float pB1 = fold2(aB1) + biasB;
                pB1 = __fmaf_rn(xv1.x, wiB[0], pB1);
                pB1 = __fmaf_rn(xv1.y, wiB[1], pB1);
                pB1 = __fmaf_rn(xv1.z, wiB[2], pB1);
                pB1 = __fmaf_rn(xv1.w, wiB[3], pB1);

                // rowA is i or f -> sigmoid. rowB: parity0 -> g (tanh), parity1 -> o (sigmoid)
                actA[s0] = fsig(pA0);
                actA[s1] = fsig(pA1);
                if (parity == 0) { actB[s0] = ftanh(pB0); actB[s1] = ftanh(pB1); }
                else             { actB[s0] = fsig(pB0);  actB[s1] = fsig(pB1); }
            }

            // exchange with pair lane: rx = partner's act values
            float rxA[S_PER_BLK], rxB[S_PER_BLK];
            #pragma unroll
            for (int s = 0; s < S_PER_BLK; s++) {
                rxA[s] = __shfl_xor_sync(0xffffffffu, actA[s], 1);
                rxB[s] = __shfl_xor_sync(0xffffffffu, actB[s], 1);
            }

            // update 2 samples: even lane -> s 0,1 (own = i,g; rx = f,o)
            //                   odd lane  -> s 2,3 (own = f,o; rx = i,g)
            float* rp = ring + p * S_PER_BLK * H_DIM;
            if (parity == 0) {
                c1a = __fmaf_rn(rxA[0], c1a, actA[0] * actB[0]);
                rp[0 * H_DIM + h] = rxB[0] * ftanh(c1a);
                c1b = __fmaf_rn(rxA[1], c1b, actA[1] * actB[1]);
                rp[1 * H_DIM + h] = rxB[1] * ftanh(c1b);
            } else {
                c1a = __fmaf_rn(actA[2], c1a, rxA[2] * rxB[2]);
                rp[2 * H_DIM + h] = actB[2] * ftanh(c1a);
                c1b = __fmaf_rn(actA[3], c1b, rxA[3] * rxB[3]);
                rp[3 * H_DIM + h] = actB[3] * ftanh(c1b);
            }

            bar_sync(BAR_L0INT, L0_SZ);                // ring[p] complete within L0
            bar_arrive(BAR_READY + p, NTHREADS);       // publish h1(t)
        }
    } else {
        // ========== L1: 256 threads. thread g owns row r = (g&3)*64 + (g>>2) ==========
        const int g    = tid - L0_SZ;
        const int h    = g >> 2;
        const int gt   = g & 3;                 // 0=i,1=f,2=g,3=o
        const int r    = gt * H_DIM + h;
        const int lane = tid & 31;
        const int qbase = lane & ~3;            // quad base lane
        const bool is_tanh = (gt == 2);

        float4 w1[16], w2[16];
        {
            const float4* p1 = (const float4*)(W_ih1 + r * H_DIM);
            const float4* p2 = (const float4*)(W_hh1 + r * H_DIM);
            #pragma unroll
            for (int i = 0; i < 16; i++) { w1[i] = p1[i]; w2[i] = p2[i]; }
        }
        const float bias1 = b1[r];
        float c2[S_PER_BLK];
        #pragma unroll
        for (int s = 0; s < S_PER_BLK; s++) c2[s] = 0.f;

        ull acc[S_PER_BLK];                     // carried h2*Whh1 partial
        #pragma unroll
        for (int s = 0; s < S_PER_BLK; s++) acc[s] = 0ULL;

        for (int t = 0; t < T_STEPS; t++) {
            const int p = t & 3;

            bar_sync(BAR_READY + p, NTHREADS);  // h1(t) ready

            const float4* h1c = (const float4*)(ring + p * S_PER_BLK * H_DIM);
            #pragma unroll
            for (int k = 0; k < 16; k++) {
                #pragma unroll
                for (int s = 0; s < S_PER_BLK; s++) {
                    const float4 hv = h1c[s * 16 + k];
                    fma2(acc[s], f4lo(w1[k]), f4lo(hv), acc[s]);
                    fma2(acc[s], f4hi(w1[k]), f4hi(hv), acc[s]);
                }
            }
            bar_arrive(BAR_FREE + p, NTHREADS); // done reading ring[p]

            float val[S_PER_BLK];
            #pragma unroll
            for (int s = 0; s < S_PER_BLK; s++) {
                float pre = fold2(acc[s]) + bias1;
                val[s] = is_tanh ? ftanh(pre) : fsig(pre);
            }

            // quad allgather + redundant update; lane gt stores sample s==gt
            #pragma unroll
            for (int s = 0; s < S_PER_BLK; s++) {
                const float iv = __shfl_sync(0xffffffffu, val[s], qbase + 0);
                const float fv = __shfl_sync(0xffffffffu, val[s], qbase + 1);
                const float gv = __shfl_sync(0xffffffffu, val[s], qbase + 2);
                const float ov = __shfl_sync(0xffffffffu, val[s], qbase + 3);
                c2[s] = __fmaf_rn(fv, c2[s], iv * gv);
                const float h2v = ov * ftanh(c2[s]);
                if (gt == s) h2s[s * H_DIM + h] = h2v;
            }

            bar_sync(BAR_L1INT, L1_SZ);         // h2(t) visible to all L1

            // precompute next step's h2*Whh1 partial (register weights)
            #pragma unroll
            for (int s = 0; s < S_PER_BLK; s++) acc[s] = 0ULL;
            #pragma unroll
            for (int k = 0; k < 16; k++) {
                #pragma unroll
                for (int s = 0; s < S_PER_BLK; s++) {
                    const float4 hv = ((const float4*)h2s)[s * 16 + k];
                    fma2(acc[s], f4lo(w2[k]), f4lo(hv), acc[s]);
                    fma2(acc[s], f4hi(w2[k]), f4hi(hv), acc[s]);
                }
            }
        }
    }

    __syncthreads();

    // ---------- classifier (ring reused as scratch) ----------
    if (tid < S_PER_BLK * 32) {
        int s = tid >> 5, j = tid & 31;
        float a = b_fc1[j];
        #pragma unroll
        for (int k = 0; k < H_DIM; k++)
            a = __fmaf_rn(h2s[s * H_DIM + k], W_fc1[j * H_DIM + k], a);
        ring[s * 32 + j] = fmaxf(a, 0.f);
    }
    __syncthreads();
    if (tid < S_PER_BLK) {
        float a = b_fc2[0];
        #pragma unroll
        for (int j = 0; j < 32; j++)
            a = __fmaf_rn(ring[tid * 32 + j], W_fc2[j], a);
        out[bb + tid] = fsig(a);
    }
}

extern "C" void kernel_launch(void* const* d_in, const int* in_sizes, int n_in,
                              void* d_out, int out_size)
{
    const float* x     = (const float*)d_in[0];
    const float* W_ih0 = (const float*)d_in[1];
    const float* W_hh0 = (const float*)d_in[2];
    const float* b0    = (const float*)d_in[3];
    const float* W_ih1 = (const float*)d_in[4];
    const float* W_hh1 = (const float*)d_in[5];
    const float* b1    = (const float*)d_in[6];
    const float* W_fc1 = (const float*)d_in[7];
    const float* b_fc1 = (const float*)d_in[8];
    const float* W_fc2 = (const float*)d_in[9];
    const float* b_fc2 = (const float*)d_in[10];
    float* out = (float*)d_out;

    const size_t smem_bytes =
        (size_t)(S_PER_BLK * T_STEPS * D_DIM          // xs
                 + RING_D * S_PER_BLK * H_DIM         // ring
                 + S_PER_BLK * H_DIM)                 // h2s
        * sizeof(float);

    cudaFuncSetAttribute(lstm_fused_kernel,
                         cudaFuncAttributeMaxDynamicSharedMemorySize,
                         (int)smem_bytes);

    const int nblocks = 512 / S_PER_BLK;   // 128
    lstm_fused_kernel<<<nblocks, NTHREADS, smem_bytes>>>(
        x, W_ih0, W_hh0, b0, W_ih1, W_hh1, b1,
        W_fc1, b_fc1, W_fc2, b_fc2, out);
}

// round 8
// speedup vs baseline: 1.1042x; 1.1042x over previous
#include <cuda_runtime.h>

#define S_PER_BLK 4
#define T_STEPS   1024
#define H_DIM     64
#define G_DIM     256   // 4*H
#define D_DIM     4
#define NTHREADS  512   // 256 L0 + 256 L1, 1 gate row each
#define L0_SZ     256
#define L1_SZ     256
#define RING_D    4
#define W2_STRIDE 68    // padded smem row stride for W_hh1 (conflict-free LDS.128)

// named barrier ids
#define BAR_L0INT  1
#define BAR_L1INT  2
#define BAR_READY  3   // 3..6  (phase p -> 3+p)
#define BAR_FREE   7   // 7..10

typedef unsigned long long ull;

__device__ __forceinline__ void bar_sync(int id, int cnt) {
    asm volatile("bar.sync %0, %1;" :: "r"(id), "r"(cnt) : "memory");
}
__device__ __forceinline__ void bar_arrive(int id, int cnt) {
    asm volatile("bar.arrive %0, %1;" :: "r"(id), "r"(cnt) : "memory");
}

// ---- fast activations ----
__device__ __forceinline__ float fsig(float x) {
    float e = __expf(-x);
    float d = 1.0f + e;
    float r;
    asm("rcp.approx.f32 %0, %1;" : "=f"(r) : "f"(d));
    return r;
}
__device__ __forceinline__ float ftanh(float x) {
    return __fmaf_rn(2.0f, fsig(2.0f * x), -1.0f);
}

// ---- packed f32x2 fma (sm_100+) ----
__device__ __forceinline__ void fma2(ull& d, ull a, ull b, ull c) {
    asm("fma.rn.f32x2 %0, %1, %2, %3;" : "=l"(d) : "l"(a), "l"(b), "l"(c));
}
__device__ __forceinline__ float fold2(ull a) {
    float lo, hi;
    asm("mov.b64 {%0,%1}, %2;" : "=f"(lo), "=f"(hi) : "l"(a));
    return lo + hi;
}
__device__ __forceinline__ ull f4lo(const float4& v) {
    ull r; asm("mov.b64 %0, {%1,%2};" : "=l"(r) : "f"(v.x), "f"(v.y)); return r;
}
__device__ __forceinline__ ull f4hi(const float4& v) {
    ull r; asm("mov.b64 %0, {%1,%2};" : "=l"(r) : "f"(v.z), "f"(v.w)); return r;
}

// smem layout (floats):
//   xs   : S*T*D        = 16384
//   w2s  : G*W2_STRIDE  = 17408   (W_hh1 padded rows; streamed in L1 shadow segment)
//   ring : RING_D*S*H   = 1024    (h1 ring, L0 -> L1; classifier scratch at the end)
//   h2s  : S*H          = 256
//   ga0  : S*G          = 1024
//   ga1  : S*G          = 1024
// total 37120 floats = 148480 bytes

__global__ __launch_bounds__(NTHREADS, 1)
void lstm_fused_kernel(const float* __restrict__ x,
                       const float* __restrict__ W_ih0,
                       const float* __restrict__ W_hh0,
                       const float* __restrict__ b0,
                       const float* __restrict__ W_ih1,
                       const float* __restrict__ W_hh1,
                       const float* __restrict__ b1,
                       const float* __restrict__ W_fc1,
                       const float* __restrict__ b_fc1,
                       const float* __restrict__ W_fc2,
                       const float* __restrict__ b_fc2,
                       float* __restrict__ out)
{
    extern __shared__ float sm[];
    float* xs   = sm;                                   // [S][T][D]
    float* w2s  = sm + S_PER_BLK * T_STEPS * D_DIM;     // [G][W2_STRIDE]
    float* ring = w2s + G_DIM * W2_STRIDE;              // [RING_D][S][H]
    float* h2s  = ring + RING_D * S_PER_BLK * H_DIM;    // [S][H]
    float* ga0  = h2s + S_PER_BLK * H_DIM;              // [S][G]
    float* ga1  = ga0 + S_PER_BLK * G_DIM;              // [S][G]

    const int tid  = threadIdx.x;
    const bool isL0 = tid < L0_SZ;
    const int g    = tid & 255;          // gate row within group
    const int bb   = blockIdx.x * S_PER_BLK;
    const int us   = g >> 6;             // update sample
    const int uh   = g & 63;             // update hidden idx
    const bool is_tanh = (g >= 2 * H_DIM) && (g < 3 * H_DIM);

    // ---- common staging ----
    {
        const float4* gx = (const float4*)(x + (size_t)bb * T_STEPS * D_DIM);
        float4*       sx = (float4*)xs;
        #pragma unroll 4
        for (int i = tid; i < S_PER_BLK * T_STEPS; i += NTHREADS) sx[i] = gx[i];
    }
    // W_hh1 -> padded smem (coalesced global reads)
    for (int i = tid; i < G_DIM * H_DIM; i += NTHREADS) {
        int row = i >> 6, col = i & 63;
        w2s[row * W2_STRIDE + col] = W_hh1[i];
    }
    for (int i = tid; i < RING_D * S_PER_BLK * H_DIM; i += NTHREADS) ring[i] = 0.f;
    for (int i = tid; i < S_PER_BLK * H_DIM; i += NTHREADS) h2s[i] = 0.f;

    __syncthreads();

    if (isL0) {
        // ============ L0: 256 threads, one W_hh0 row in regs (64 regs) ============
        float4 w0[16];
        {
            const float4* p0 = (const float4*)(W_hh0 + g * H_DIM);
            #pragma unroll
            for (int i = 0; i < 16; i++) w0[i] = p0[i];
        }
        float wi0[D_DIM];
        #pragma unroll
        for (int d = 0; d < D_DIM; d++) wi0[d] = W_ih0[g * D_DIM + d];
        const float bias0 = b0[g];
        float c1r = 0.f;

        for (int t = 0; t < T_STEPS; t++) {
            const int p = t & 3;
            if (t >= RING_D) bar_sync(BAR_FREE + p, NTHREADS);  // slot p reusable

            const float4* h1p = (const float4*)(ring + ((t - 1) & 3) * S_PER_BLK * H_DIM);

            ull acc[S_PER_BLK];
            #pragma unroll
            for (int s = 0; s < S_PER_BLK; s++) acc[s] = 0ULL;
            #pragma unroll
            for (int k = 0; k < 16; k++) {
                #pragma unroll
                for (int s = 0; s < S_PER_BLK; s++) {
                    const float4 hv = h1p[s * 16 + k];
                    fma2(acc[s], f4lo(w0[k]), f4lo(hv), acc[s]);
                    fma2(acc[s], f4hi(w0[k]), f4hi(hv), acc[s]);
                }
            }
            #pragma unroll
            for (int s = 0; s < S_PER_BLK; s++) {
                const float4 xv = ((const float4*)xs)[s * T_STEPS + t];
                float pre = fold2(acc[s]) + bias0;
                pre = __fmaf_rn(xv.x, wi0[0], pre);
                pre = __fmaf_rn(xv.y, wi0[1], pre);
                pre = __fmaf_rn(xv.z, wi0[2], pre);
                pre = __fmaf_rn(xv.w, wi0[3], pre);
                ga0[s * G_DIM + g] = is_tanh ? ftanh(pre) : fsig(pre);
            }
            bar_sync(BAR_L0INT, L0_SZ);                 // ga0 ready

            // state update: one (s,h) per thread -> ring[p]
            {
                const float iv = ga0[us * G_DIM + uh];
                const float fv = ga0[us * G_DIM + uh + H_DIM];
                const float gv = ga0[us * G_DIM + uh + 2 * H_DIM];
                const float ov = ga0[us * G_DIM + uh + 3 * H_DIM];
                c1r = __fmaf_rn(fv, c1r, iv * gv);
                ring[p * S_PER_BLK * H_DIM + us * H_DIM + uh] = ov * ftanh(c1r);
            }
            bar_sync(BAR_L0INT, L0_SZ);                 // ring[p] complete
            bar_arrive(BAR_READY + p, NTHREADS);        // publish h1(t)
        }
    } else {
        // ============ L1: 256 threads, W_ih1 row in regs, W_hh1 row from smem ============
        float4 w1[16];
        {
            const float4* p1 = (const float4*)(W_ih1 + g * H_DIM);
            #pragma unroll
            for (int i = 0; i < 16; i++) w1[i] = p1[i];
        }
        const float bias1 = b1[g];
        float c2r = 0.f;
        const float4* w2row = (const float4*)(w2s + g * W2_STRIDE);

        ull acc[S_PER_BLK];              // carried h2*Whh1 partial
        #pragma unroll
        for (int s = 0; s < S_PER_BLK; s++) acc[s] = 0ULL;   // h2(-1)=0

        for (int t = 0; t < T_STEPS; t++) {
            const int p = t & 3;

            bar_sync(BAR_READY + p, NTHREADS);          // h1(t) ready

            // critical segment: add h1(t)*Wih1 (register weights)
            const float4* h1c = (const float4*)(ring + p * S_PER_BLK * H_DIM);
            #pragma unroll
            for (int k = 0; k < 16; k++) {
                #pragma unroll
                for (int s = 0; s < S_PER_BLK; s++) {
                    const float4 hv = h1c[s * 16 + k];
                    fma2(acc[s], f4lo(w1[k]), f4lo(hv), acc[s]);
                    fma2(acc[s], f4hi(w1[k]), f4hi(hv), acc[s]);
                }
            }
            bar_arrive(BAR_FREE + p, NTHREADS);         // done reading ring[p]

            #pragma unroll
            for (int s = 0; s < S_PER_BLK; s++) {
                float pre = fold2(acc[s]) + bias1;
                ga1[s * G_DIM + g] = is_tanh ? ftanh(pre) : fsig(pre);
            }
            bar_sync(BAR_L1INT, L1_SZ);                 // ga1 ready

            // layer-1 state update: one (s,h) per thread
            {
                const float iv = ga1[us * G_DIM + uh];
                const float fv = ga1[us * G_DIM + uh + H_DIM];
                const float gv = ga1[us * G_DIM + uh + 2 * H_DIM];
                const float ov = ga1[us * G_DIM + uh + 3 * H_DIM];
                c2r = __fmaf_rn(fv, c2r, iv * gv);
                h2s[us * H_DIM + uh] = ov * ftanh(c2r);
            }
            bar_sync(BAR_L1INT, L1_SZ);                 // h2(t) visible

            // shadow segment: next step's h2*Whh1 partial (weights streamed from smem)
            #pragma unroll
            for (int s = 0; s < S_PER_BLK; s++) acc[s] = 0ULL;
            #pragma unroll
            for (int k = 0; k < 16; k++) {
                const float4 wv = w2row[k];
                #pragma unroll
                for (int s = 0; s < S_PER_BLK; s++) {
                    const float4 hv = ((const float4*)h2s)[s * 16 + k];
                    fma2(acc[s], f4lo(wv), f4lo(hv), acc[s]);
                    fma2(acc[s], f4hi(wv), f4hi(hv), acc[s]);
                }
            }
        }
    }

    __syncthreads();

    // ---------- classifier (ring reused as scratch) ----------
    if (tid < S_PER_BLK * 32) {
        int s = tid >> 5, j = tid & 31;
        float a = b_fc1[j];
        #pragma unroll
        for (int k = 0; k < H_DIM; k++)
            a = __fmaf_rn(h2s[s * H_DIM + k], W_fc1[j * H_DIM + k], a);
        ring[s * 32 + j] = fmaxf(a, 0.f);
    }
    __syncthreads();
    if (tid < S_PER_BLK) {
        float a = b_fc2[0];
        #pragma unroll
        for (int j = 0; j < 32; j++)
            a = __fmaf_rn(ring[tid * 32 + j], W_fc2[j], a);
        out[bb + tid] = fsig(a);
    }
}

extern "C" void kernel_launch(void* const* d_in, const int* in_sizes, int n_in,
                              void* d_out, int out_size)
{
    const float* x     = (const float*)d_in[0];
    const float* W_ih0 = (const float*)d_in[1];
    const float* W_hh0 = (const float*)d_in[2];
    const float* b0    = (const float*)d_in[3];
    const float* W_ih1 = (const float*)d_in[4];
    const float* W_hh1 = (const float*)d_in[5];
    const float* b1    = (const float*)d_in[6];
    const float* W_fc1 = (const float*)d_in[7];
    const float* b_fc1 = (const float*)d_in[8];
    const float* W_fc2 = (const float*)d_in[9];
    const float* b_fc2 = (const float*)d_in[10];
    float* out = (float*)d_out;

    const size_t smem_bytes =
        (size_t)(S_PER_BLK * T_STEPS * D_DIM          // xs
                 + G_DIM * W2_STRIDE                  // w2s
                 + RING_D * S_PER_BLK * H_DIM         // ring
                 + S_PER_BLK * H_DIM                  // h2s
                 + 2 * S_PER_BLK * G_DIM)             // ga0, ga1
        * sizeof(float);

    cudaFuncSetAttribute(lstm_fused_kernel,
                         cudaFuncAttributeMaxDynamicSharedMemorySize,
                         (int)smem_bytes);

    const int nblocks = 512 / S_PER_BLK;   // 128
    lstm_fused_kernel<<<nblocks, NTHREADS, smem_bytes>>>(
        x, W_ih0, W_hh0, b0, W_ih1, W_hh1, b1,
        W_fc1, b_fc1, W_fc2, b_fc2, out);
}

// round 9
// speedup vs baseline: 1.2921x; 1.1702x over previous
#include <cuda_runtime.h>

#define S_PER_BLK 4
#define T_STEPS   1024
#define H_DIM     64
#define G_DIM     256   // 4*H
#define D_DIM     4
#define NTHREADS  384   // 128 L0 threads (2 rows each) + 256 L1 threads (1 row)
#define L0_SZ     128
#define L1_SZ     256
#define RING_D    4

// named barrier ids
#define BAR_L0INT  1
#define BAR_L1INT  2
#define BAR_READY  3   // 3..6  (phase p -> 3+p)
#define BAR_FREE   7   // 7..10

typedef unsigned long long ull;

__device__ __forceinline__ void bar_sync(int id, int cnt) {
    asm volatile("bar.sync %0, %1;" :: "r"(id), "r"(cnt) : "memory");
}
__device__ __forceinline__ void bar_arrive(int id, int cnt) {
    asm volatile("bar.arrive %0, %1;" :: "r"(id), "r"(cnt) : "memory");
}

// ---- fast activations: single-MUFU tanh.approx (sm_75+) ----
__device__ __forceinline__ float ftanh(float x) {
    float r;
    asm("tanh.approx.f32 %0, %1;" : "=f"(r) : "f"(x));
    return r;
}
__device__ __forceinline__ float fsig(float x) {
    float r;
    asm("tanh.approx.f32 %0, %1;" : "=f"(r) : "f"(0.5f * x));
    return __fmaf_rn(0.5f, r, 0.5f);
}

// ---- packed f32x2 fma (sm_100+) ----
__device__ __forceinline__ void fma2(ull& d, ull a, ull b, ull c) {
    asm("fma.rn.f32x2 %0, %1, %2, %3;" : "=l"(d) : "l"(a), "l"(b), "l"(c));
}
__device__ __forceinline__ float fold2(ull a) {
    float lo, hi;
    asm("mov.b64 {%0,%1}, %2;" : "=f"(lo), "=f"(hi) : "l"(a));
    return lo + hi;
}
__device__ __forceinline__ ull packf2(float lo, float hi) {
    ull r; asm("mov.b64 %0, {%1,%2};" : "=l"(r) : "f"(lo), "f"(hi)); return r;
}
__device__ __forceinline__ ull f4lo(const float4& v) {
    ull r; asm("mov.b64 %0, {%1,%2};" : "=l"(r) : "f"(v.x), "f"(v.y)); return r;
}
__device__ __forceinline__ ull f4hi(const float4& v) {
    ull r; asm("mov.b64 %0, {%1,%2};" : "=l"(r) : "f"(v.z), "f"(v.w)); return r;
}

// smem layout (floats):
//   xs   : S*T*D        = 16384
//   ring : RING_D*S*H   = 1024   (h1 ring; classifier scratch afterward)
//   h2s  : S*H          = 256
//   ga0  : S*G          = 1024
//   ga1  : S*G          = 1024
// total 19712 floats = 78848 bytes

__global__ __launch_bounds__(NTHREADS, 1)
void lstm_fused_kernel(const float* __restrict__ x,
                       const float* __restrict__ W_ih0,
                       const float* __restrict__ W_hh0,
                       const float* __restrict__ b0,
                       const float* __restrict__ W_ih1,
                       const float* __restrict__ W_hh1,
                       const float* __restrict__ b1,
                       const float* __restrict__ W_fc1,
                       const float* __restrict__ b_fc1,
                       const float* __restrict__ W_fc2,
                       const float* __restrict__ b_fc2,
                       float* __restrict__ out)
{
    extern __shared__ float sm[];
    float* xs   = sm;                                   // [S][T][D]
    float* ring = sm + S_PER_BLK * T_STEPS * D_DIM;     // [RING_D][S][H]
    float* h2s  = ring + RING_D * S_PER_BLK * H_DIM;    // [S][H]
    float* ga0  = h2s + S_PER_BLK * H_DIM;              // [S][G]
    float* ga1  = ga0 + S_PER_BLK * G_DIM;              // [S][G]

    const int tid  = threadIdx.x;
    const bool isL0 = tid < L0_SZ;
    const int bb   = blockIdx.x * S_PER_BLK;

    // ---- common staging ----
    {
        const float4* gx = (const float4*)(x + (size_t)bb * T_STEPS * D_DIM);
        float4*       sx = (float4*)xs;
        #pragma unroll 4
        for (int i = tid; i < S_PER_BLK * T_STEPS; i += NTHREADS) sx[i] = gx[i];
    }
    for (int i = tid; i < RING_D * S_PER_BLK * H_DIM; i += NTHREADS) ring[i] = 0.f;
    for (int i = tid; i < S_PER_BLK * H_DIM; i += NTHREADS) h2s[i] = 0.f;

    __syncthreads();

    if (isL0) {
        // ========== L0: 128 threads, rows gA=tid and gB=tid+128 of layer 0 ==========
        const int gA = tid;          // [0,128): i or f gate -> sigmoid
        const int gB = tid + 128;    // [128,256): g (tanh) if tid<64 else o (sigmoid)
        const bool tanhB = (tid < 64);

        float4 w0a[16], w0b[16];
        {
            const float4* pa = (const float4*)(W_hh0 + gA * H_DIM);
            const float4* pb = (const float4*)(W_hh0 + gB * H_DIM);
            #pragma unroll
            for (int i = 0; i < 16; i++) { w0a[i] = pa[i]; w0b[i] = pb[i]; }
        }
        float wiA[D_DIM], wiB[D_DIM];
        #pragma unroll
        for (int d = 0; d < D_DIM; d++) {
            wiA[d] = W_ih0[gA * D_DIM + d];
            wiB[d] = W_ih0[gB * D_DIM + d];
        }
        const float biasA = b0[gA];
        const float biasB = b0[gB];

        // update ownership: (s,h) pairs 2*tid and 2*tid+1
        const int p0s = (2 * tid) >> 6, p0h = (2 * tid) & 63;
        const int p1s = (2 * tid + 1) >> 6, p1h = (2 * tid + 1) & 63;
        float c1r0 = 0.f, c1r1 = 0.f;

        for (int t = 0; t < T_STEPS; t++) {
            const int p = t & 3;
            // unconditional: primed by L1's pre-loop arrives. Also orders our
            // own ring writes from t-1 before the reads below.
            bar_sync(BAR_FREE + p, NTHREADS);

            const float4* h1p = (const float4*)(ring + ((t - 1) & 3) * S_PER_BLK * H_DIM);

            // two sample-half passes; acc preloaded with bias + x-part
            #pragma unroll
            for (int half = 0; half < 2; half++) {
                const int s0 = 2 * half, s1 = s0 + 1;
                const float4 xv0 = ((const float4*)xs)[s0 * T_STEPS + t];
                const float4 xv1 = ((const float4*)xs)[s1 * T_STEPS + t];

                float iA0 = biasA, iA1 = biasA, iB0 = biasB, iB1 = biasB;
                iA0 = __fmaf_rn(xv0.x, wiA[0], iA0); iA0 = __fmaf_rn(xv0.y, wiA[1], iA0);
                iA0 = __fmaf_rn(xv0.z, wiA[2], iA0); iA0 = __fmaf_rn(xv0.w, wiA[3], iA0);
                iA1 = __fmaf_rn(xv1.x, wiA[0], iA1); iA1 = __fmaf_rn(xv1.y, wiA[1], iA1);
                iA1 = __fmaf_rn(xv1.z, wiA[2], iA1); iA1 = __fmaf_rn(xv1.w, wiA[3], iA1);
                iB0 = __fmaf_rn(xv0.x, wiB[0], iB0); iB0 = __fmaf_rn(xv0.y, wiB[1], iB0);
                iB0 = __fmaf_rn(xv0.z, wiB[2], iB0); iB0 = __fmaf_rn(xv0.w, wiB[3], iB0);
                iB1 = __fmaf_rn(xv1.x, wiB[0], iB1); iB1 = __fmaf_rn(xv1.y, wiB[1], iB1);
                iB1 = __fmaf_rn(xv1.z, wiB[2], iB1); iB1 = __fmaf_rn(xv1.w, wiB[3], iB1);

                ull aA0 = packf2(iA0, 0.f), aA1 = packf2(iA1, 0.f);
                ull aB0 = packf2(iB0, 0.f), aB1 = packf2(iB1, 0.f);
                #pragma unroll
                for (int k = 0; k < 16; k++) {
                    const float4 hv0 = h1p[s0 * 16 + k];
                    const float4 hv1 = h1p[s1 * 16 + k];
                    fma2(aA0, f4lo(w0a[k]), f4lo(hv0), aA0);
                    fma2(aA0, f4hi(w0a[k]), f4hi(hv0), aA0);
                    fma2(aA1, f4lo(w0a[k]), f4lo(hv1), aA1);
                    fma2(aA1, f4hi(w0a[k]), f4hi(hv1), aA1);
                    fma2(aB0, f4lo(w0b[k]), f4lo(hv0), aB0);
                    fma2(aB0, f4hi(w0b[k]), f4hi(hv0), aB0);
                    fma2(aB1, f4lo(w0b[k]), f4lo(hv1), aB1);
                    fma2(aB1, f4hi(w0b[k]), f4hi(hv1), aB1);
                }
                ga0[s0 * G_DIM + gA] = fsig(fold2(aA0));
                ga0[s1 * G_DIM + gA] = fsig(fold2(aA1));
                ga0[s0 * G_DIM + gB] = tanhB ? ftanh(fold2(aB0)) : fsig(fold2(aB0));
                ga0[s1 * G_DIM + gB] = tanhB ? ftanh(fold2(aB1)) : fsig(fold2(aB1));
            }
            bar_sync(BAR_L0INT, L0_SZ);                     // ga0 ready

            // state update: 2 (s,h) pairs -> ring[p]
            {
                float iv = ga0[p0s * G_DIM + p0h];
                float fv = ga0[p0s * G_DIM + p0h + H_DIM];
                float gv = ga0[p0s * G_DIM + p0h + 2 * H_DIM];
                float ov = ga0[p0s * G_DIM + p0h + 3 * H_DIM];
                c1r0 = __fmaf_rn(fv, c1r0, iv * gv);
                ring[p * S_PER_BLK * H_DIM + p0s * H_DIM + p0h] = ov * ftanh(c1r0);

                iv = ga0[p1s * G_DIM + p1h];
                fv = ga0[p1s * G_DIM + p1h + H_DIM];
                gv = ga0[p1s * G_DIM + p1h + 2 * H_DIM];
                ov = ga0[p1s * G_DIM + p1h + 3 * H_DIM];
                c1r1 = __fmaf_rn(fv, c1r1, iv * gv);
                ring[p * S_PER_BLK * H_DIM + p1s * H_DIM + p1h] = ov * ftanh(c1r1);
            }
            // publish h1(t): arrive-release pairs with L1's sync-acquire
            bar_arrive(BAR_READY + p, NTHREADS);
        }
    } else {
        // ========== L1: 256 threads, 1 row, W_ih1 + W_hh1 both in regs ==========
        const int g = tid - L0_SZ;
        const bool is_tanh = (g >= 2 * H_DIM) && (g < 3 * H_DIM);
        const int us = g >> 6, uh = g & 63;

        float4 w1[16], w2[16];
        {
            const float4* q1 = (const float4*)(W_ih1 + g * H_DIM);
            const float4* q2 = (const float4*)(W_hh1 + g * H_DIM);
            #pragma unroll
            for (int i = 0; i < 16; i++) { w1[i] = q1[i]; w2[i] = q2[i]; }
        }
        const float bias1 = b1[g];
        float c2r = 0.f;

        // prime the FREE barriers (RING_D slots initially free)
        #pragma unroll
        for (int p = 0; p < RING_D; p++) bar_arrive(BAR_FREE + p, NTHREADS);

        ull acc[S_PER_BLK];              // carried h2*Whh1 partial, preloaded with bias
        #pragma unroll
        for (int s = 0; s < S_PER_BLK; s++) acc[s] = packf2(bias1, 0.f);  // h2(-1)=0

        for (int t = 0; t < T_STEPS; t++) {
            const int p = t & 3;

            bar_sync(BAR_READY + p, NTHREADS);          // h1(t) ready (acquire)

            const float4* h1c = (const float4*)(ring + p * S_PER_BLK * H_DIM);
            #pragma unroll
            for (int k = 0; k < 16; k++) {
                #pragma unroll
                for (int s = 0; s < S_PER_BLK; s++) {
                    const float4 hv = h1c[s * 16 + k];
                    fma2(acc[s], f4lo(w1[k]), f4lo(hv), acc[s]);
                    fma2(acc[s], f4hi(w1[k]), f4hi(hv), acc[s]);
                }
            }
            bar_arrive(BAR_FREE + p, NTHREADS);         // done reading ring[p]

            #pragma unroll
            for (int s = 0; s < S_PER_BLK; s++) {
                const float pre = fold2(acc[s]);
                ga1[s * G_DIM + g] = is_tanh ? ftanh(pre) : fsig(pre);
            }
            bar_sync(BAR_L1INT, L1_SZ);                 // ga1 ready

            {
                const float iv = ga1[us * G_DIM + uh];
                const float fv = ga1[us * G_DIM + uh + H_DIM];
                const float gv = ga1[us * G_DIM + uh + 2 * H_DIM];
                const float ov = ga1[us * G_DIM + uh + 3 * H_DIM];
                c2r = __fmaf_rn(fv, c2r, iv * gv);
                h2s[us * H_DIM + uh] = ov * ftanh(c2r);
            }
            bar_sync(BAR_L1INT, L1_SZ);                 // h2(t) visible

            // shadow: next step's h2*Whh1 partial (register weights), bias preloaded
            #pragma unroll
            for (int s = 0; s < S_PER_BLK; s++) acc[s] = packf2(bias1, 0.f);
            #pragma unroll
            for (int k = 0; k < 16; k++) {
                #pragma unroll
                for (int s = 0; s < S_PER_BLK; s++) {
                    const float4 hv = ((const float4*)h2s)[s * 16 + k];
                    fma2(acc[s], f4lo(w2[k]), f4lo(hv), acc[s]);
                    fma2(acc[s], f4hi(w2[k]), f4hi(hv), acc[s]);
                }
            }
        }
    }

    __syncthreads();

    // ---------- classifier (ring reused as scratch) ----------
    if (tid < S_PER_BLK * 32) {
        int s = tid >> 5, j = tid & 31;
        float a = b_fc1[j];
        #pragma unroll
        for (int k = 0; k < H_DIM; k++)
            a = __fmaf_rn(h2s[s * H_DIM + k], W_fc1[j * H_DIM + k], a);
        ring[s * 32 + j] = fmaxf(a, 0.f);
    }
    __syncthreads();
    if (tid < S_PER_BLK) {
        float a = b_fc2[0];
        #pragma unroll
        for (int j = 0; j < 32; j++)
            a = __fmaf_rn(ring[tid * 32 + j], W_fc2[j], a);
        out[bb + tid] = fsig(a);
    }
}

extern "C" void kernel_launch(void* const* d_in, const int* in_sizes, int n_in,
                              void* d_out, int out_size)
{
    const float* x     = (const float*)d_in[0];
    const float* W_ih0 = (const float*)d_in[1];
    const float* W_hh0 = (const float*)d_in[2];
    const float* b0    = (const float*)d_in[3];
    const float* W_ih1 = (const float*)d_in[4];
    const float* W_hh1 = (const float*)d_in[5];
    const float* b1    = (const float*)d_in[6];
    const float* W_fc1 = (const float*)d_in[7];
    const float* b_fc1 = (const float*)d_in[8];
    const float* W_fc2 = (const float*)d_in[9];
    const float* b_fc2 = (const float*)d_in[10];
    float* out = (float*)d_out;

    const size_t smem_bytes =
        (size_t)(S_PER_BLK * T_STEPS * D_DIM          // xs
                 + RING_D * S_PER_BLK * H_DIM         // ring
                 + S_PER_BLK * H_DIM                  // h2s
                 + 2 * S_PER_BLK * G_DIM)             // ga0, ga1
        * sizeof(float);

    cudaFuncSetAttribute(lstm_fused_kernel,
                         cudaFuncAttributeMaxDynamicSharedMemorySize,
                         (int)smem_bytes);

    const int nblocks = 512 / S_PER_BLK;   // 128
    lstm_fused_kernel<<<nblocks, NTHREADS, smem_bytes>>>(
        x, W_ih0, W_hh0, b0, W_ih1, W_hh1, b1,
        W_fc1, b_fc1, W_fc2, b_fc2, out);
}

// round 10
// speedup vs baseline: 1.4479x; 1.1206x over previous
#include <cuda_runtime.h>

#define S_PER_BLK 4
#define T_STEPS   1024
#define H_DIM     64
#define G_DIM     256   // 4*H
#define D_DIM     4
#define NTHREADS  384   // 3 groups x 128
#define GRP       128
#define RING_D    4

// named barrier ids (0 reserved for __syncthreads)
#define BAR_L0INT  1
#define BAR_GA1    2
#define BAR_READY  3   // 3..6   (phase p -> 3+p)   G0 arrive / G1 sync, count 256
#define BAR_FREE   7   // 7..10  G1 arrive / G0 sync, count 256
#define BAR_H2RDY  11  // 11..12 (q)  G1 arrive / G2 sync, count 256
#define BAR_PART2  13  // 13..14 (q)  G2 arrive / G1 sync, count 256

typedef unsigned long long ull;

__device__ __forceinline__ void bar_sync(int id, int cnt) {
    asm volatile("bar.sync %0, %1;" :: "r"(id), "r"(cnt) : "memory");
}
__device__ __forceinline__ void bar_arrive(int id, int cnt) {
    asm volatile("bar.arrive %0, %1;" :: "r"(id), "r"(cnt) : "memory");
}

// ---- fast activations: single-MUFU tanh.approx ----
__device__ __forceinline__ float ftanh(float x) {
    float r;
    asm("tanh.approx.f32 %0, %1;" : "=f"(r) : "f"(x));
    return r;
}
__device__ __forceinline__ float fsig(float x) {
    float r;
    asm("tanh.approx.f32 %0, %1;" : "=f"(r) : "f"(0.5f * x));
    return __fmaf_rn(0.5f, r, 0.5f);
}

// ---- packed f32x2 fma (sm_100+) ----
__device__ __forceinline__ void fma2(ull& d, ull a, ull b, ull c) {
    asm("fma.rn.f32x2 %0, %1, %2, %3;" : "=l"(d) : "l"(a), "l"(b), "l"(c));
}
__device__ __forceinline__ float fold2(ull a) {
    float lo, hi;
    asm("mov.b64 {%0,%1}, %2;" : "=f"(lo), "=f"(hi) : "l"(a));
    return lo + hi;
}
__device__ __forceinline__ ull packf2(float lo, float hi) {
    ull r; asm("mov.b64 %0, {%1,%2};" : "=l"(r) : "f"(lo), "f"(hi)); return r;
}
__device__ __forceinline__ ull f4lo(const float4& v) {
    ull r; asm("mov.b64 %0, {%1,%2};" : "=l"(r) : "f"(v.x), "f"(v.y)); return r;
}
__device__ __forceinline__ ull f4hi(const float4& v) {
    ull r; asm("mov.b64 %0, {%1,%2};" : "=l"(r) : "f"(v.z), "f"(v.w)); return r;
}

// smem layout (floats):
//   xs   : S*T*D      = 16384
//   ring : RING_D*S*H = 1024   (h1 ring, G0 -> G1)
//   h2s  : 2*S*H      = 512    (h2 double buffer, G1 -> G2)
//   ga0  : S*G        = 1024   (layer-0 gate exchange; classifier scratch)
//   ga1  : S*G        = 1024   (layer-1 gate exchange)
//   pp   : 2*S*G      = 2048   (part2 double buffer, G2 -> G1)
// total 22016 floats = 88064 bytes

__global__ __launch_bounds__(NTHREADS, 1)
void lstm_fused_kernel(const float* __restrict__ x,
                       const float* __restrict__ W_ih0,
                       const float* __restrict__ W_hh0,
                       const float* __restrict__ b0,
                       const float* __restrict__ W_ih1,
                       const float* __restrict__ W_hh1,
                       const float* __restrict__ b1,
                       const float* __restrict__ W_fc1,
                       const float* __restrict__ b_fc1,
                       const float* __restrict__ W_fc2,
                       const float* __restrict__ b_fc2,
                       float* __restrict__ out)
{
    extern __shared__ float sm[];
    float* xs   = sm;                                   // [S][T][D]
    float* ring = sm + S_PER_BLK * T_STEPS * D_DIM;     // [RING_D][S][H]
    float* h2s  = ring + RING_D * S_PER_BLK * H_DIM;    // [2][S][H]
    float* ga0  = h2s + 2 * S_PER_BLK * H_DIM;          // [S][G]
    float* ga1  = ga0 + S_PER_BLK * G_DIM;              // [S][G]
    float* pp   = ga1 + S_PER_BLK * G_DIM;              // [2][S][G]

    const int tid = threadIdx.x;
    const int bb  = blockIdx.x * S_PER_BLK;

    // ---- common staging ----
    {
        const float4* gx = (const float4*)(x + (size_t)bb * T_STEPS * D_DIM);
        float4*       sx = (float4*)xs;
        #pragma unroll 4
        for (int i = tid; i < S_PER_BLK * T_STEPS; i += NTHREADS) sx[i] = gx[i];
    }
    for (int i = tid; i < RING_D * S_PER_BLK * H_DIM; i += NTHREADS) ring[i] = 0.f;
    for (int i = tid; i < 2 * S_PER_BLK * H_DIM; i += NTHREADS) h2s[i] = 0.f;

    __syncthreads();

    if (tid < GRP) {
        // ========== G0: layer 0, rows gA=tid, gB=tid+128 (R9-proven) ==========
        const int gA = tid;
        const int gB = tid + 128;
        const bool tanhB = (tid < 64);

        float4 w0a[16], w0b[16];
        {
            const float4* pa = (const float4*)(W_hh0 + gA * H_DIM);
            const float4* pb = (const float4*)(W_hh0 + gB * H_DIM);
            #pragma unroll
            for (int i = 0; i < 16; i++) { w0a[i] = pa[i]; w0b[i] = pb[i]; }
        }
        float wiA[D_DIM], wiB[D_DIM];
        #pragma unroll
        for (int d = 0; d < D_DIM; d++) {
            wiA[d] = W_ih0[gA * D_DIM + d];
            wiB[d] = W_ih0[gB * D_DIM + d];
        }
        const float biasA = b0[gA];
        const float biasB = b0[gB];

        const int p0s = (2 * tid) >> 6, p0h = (2 * tid) & 63;
        const int p1s = (2 * tid + 1) >> 6, p1h = (2 * tid + 1) & 63;
        float c1r0 = 0.f, c1r1 = 0.f;

        for (int t = 0; t < T_STEPS; t++) {
            const int p = t & 3;
            bar_sync(BAR_FREE + p, 2 * GRP);   // primed by G1; slot p reusable

            const float4* h1p = (const float4*)(ring + ((t - 1) & 3) * S_PER_BLK * H_DIM);

            #pragma unroll
            for (int half = 0; half < 2; half++) {
                const int s0 = 2 * half, s1 = s0 + 1;
                const float4 xv0 = ((const float4*)xs)[s0 * T_STEPS + t];
                const float4 xv1 = ((const float4*)xs)[s1 * T_STEPS + t];

                float iA0 = biasA, iA1 = biasA, iB0 = biasB, iB1 = biasB;
                iA0 = __fmaf_rn(xv0.x, wiA[0], iA0); iA0 = __fmaf_rn(xv0.y, wiA[1], iA0);
                iA0 = __fmaf_rn(xv0.z, wiA[2], iA0); iA0 = __fmaf_rn(xv0.w, wiA[3], iA0);
                iA1 = __fmaf_rn(xv1.x, wiA[0], iA1); iA1 = __fmaf_rn(xv1.y, wiA[1], iA1);
                iA1 = __fmaf_rn(xv1.z, wiA[2], iA1); iA1 = __fmaf_rn(xv1.w, wiA[3], iA1);
                iB0 = __fmaf_rn(xv0.x, wiB[0], iB0); iB0 = __fmaf_rn(xv0.y, wiB[1], iB0);
                iB0 = __fmaf_rn(xv0.z, wiB[2], iB0); iB0 = __fmaf_rn(xv0.w, wiB[3], iB0);
                iB1 = __fmaf_rn(xv1.x, wiB[0], iB1); iB1 = __fmaf_rn(xv1.y, wiB[1], iB1);
                iB1 = __fmaf_rn(xv1.z, wiB[2], iB1); iB1 = __fmaf_rn(xv1.w, wiB[3], iB1);

                ull aA0 = packf2(iA0, 0.f), aA1 = packf2(iA1, 0.f);
                ull aB0 = packf2(iB0, 0.f), aB1 = packf2(iB1, 0.f);
                #pragma unroll
                for (int k = 0; k < 16; k++) {
                    const float4 hv0 = h1p[s0 * 16 + k];
                    const float4 hv1 = h1p[s1 * 16 + k];
                    fma2(aA0, f4lo(w0a[k]), f4lo(hv0), aA0);
                    fma2(aA0, f4hi(w0a[k]), f4hi(hv0), aA0);
                    fma2(aA1, f4lo(w0a[k]), f4lo(hv1), aA1);
                    fma2(aA1, f4hi(w0a[k]), f4hi(hv1), aA1);
                    fma2(aB0, f4lo(w0b[k]), f4lo(hv0), aB0);
                    fma2(aB0, f4hi(w0b[k]), f4hi(hv0), aB0);
                    fma2(aB1, f4lo(w0b[k]), f4lo(hv1), aB1);
                    fma2(aB1, f4hi(w0b[k]), f4hi(hv1), aB1);
                }
                ga0[s0 * G_DIM + gA] = fsig(fold2(aA0));
                ga0[s1 * G_DIM + gA] = fsig(fold2(aA1));
                ga0[s0 * G_DIM + gB] = tanhB ? ftanh(fold2(aB0)) : fsig(fold2(aB0));
                ga0[s1 * G_DIM + gB] = tanhB ? ftanh(fold2(aB1)) : fsig(fold2(aB1));
            }
            bar_sync(BAR_L0INT, GRP);                   // ga0 ready

            {
                float iv = ga0[p0s * G_DIM + p0h];
                float fv = ga0[p0s * G_DIM + p0h + H_DIM];
                float gv = ga0[p0s * G_DIM + p0h + 2 * H_DIM];
                float ov = ga0[p0s * G_DIM + p0h + 3 * H_DIM];
                c1r0 = __fmaf_rn(fv, c1r0, iv * gv);
                ring[p * S_PER_BLK * H_DIM + p0s * H_DIM + p0h] = ov * ftanh(c1r0);

                iv = ga0[p1s * G_DIM + p1h];
                fv = ga0[p1s * G_DIM + p1h + H_DIM];
                gv = ga0[p1s * G_DIM + p1h + 2 * H_DIM];
                ov = ga0[p1s * G_DIM + p1h + 3 * H_DIM];
                c1r1 = __fmaf_rn(fv, c1r1, iv * gv);
                ring[p * S_PER_BLK * H_DIM + p1s * H_DIM + p1h] = ov * ftanh(c1r1);
            }
            bar_arrive(BAR_READY + p, 2 * GRP);         // publish h1(t) to G1
        }
    } else if (tid < 2 * GRP) {
        // ========== G1: critical path. rows rA=t1, rB=t1+128 of layer 1 ==========
        const int t1 = tid - GRP;
        const int rA = t1;
        const int rB = t1 + 128;
        const bool tanhB = (t1 < 64);

        float4 w1a[16], w1b[16];
        {
            const float4* pa = (const float4*)(W_ih1 + rA * H_DIM);
            const float4* pb = (const float4*)(W_ih1 + rB * H_DIM);
            #pragma unroll
            for (int i = 0; i < 16; i++) { w1a[i] = pa[i]; w1b[i] = pb[i]; }
        }

        const int p0s = (2 * t1) >> 6, p0h = (2 * t1) & 63;
        const int p1s = (2 * t1 + 1) >> 6, p1h = (2 * t1 + 1) & 63;
        float c2r0 = 0.f, c2r1 = 0.f;

        // prime: RING_D free slots; h2(-1) "ready" in h2s[1]
        #pragma unroll
        for (int p = 0; p < RING_D; p++) bar_arrive(BAR_FREE + p, 2 * GRP);
        bar_arrive(BAR_H2RDY + 1, 2 * GRP);

        for (int t = 0; t < T_STEPS; t++) {
            const int p = t & 3;
            const int q = t & 1;

            bar_sync(BAR_READY + p, 2 * GRP);           // h1(t) ready

            const float4* h1c = (const float4*)(ring + p * S_PER_BLK * H_DIM);
            float preA[S_PER_BLK], preB[S_PER_BLK];
            #pragma unroll
            for (int half = 0; half < 2; half++) {
                const int s0 = 2 * half, s1 = s0 + 1;
                ull aA0 = 0, aA1 = 0, aB0 = 0, aB1 = 0;
                #pragma unroll
                for (int k = 0; k < 16; k++) {
                    const float4 hv0 = h1c[s0 * 16 + k];
                    const float4 hv1 = h1c[s1 * 16 + k];
                    fma2(aA0, f4lo(w1a[k]), f4lo(hv0), aA0);
                    fma2(aA0, f4hi(w1a[k]), f4hi(hv0), aA0);
                    fma2(aA1, f4lo(w1a[k]), f4lo(hv1), aA1);
                    fma2(aA1, f4hi(w1a[k]), f4hi(hv1), aA1);
                    fma2(aB0, f4lo(w1b[k]), f4lo(hv0), aB0);
                    fma2(aB0, f4hi(w1b[k]), f4hi(hv0), aB0);
                    fma2(aB1, f4lo(w1b[k]), f4lo(hv1), aB1);
                    fma2(aB1, f4hi(w1b[k]), f4hi(hv1), aB1);
                }
                preA[s0] = fold2(aA0); preA[s1] = fold2(aA1);
                preB[s0] = fold2(aB0); preB[s1] = fold2(aB1);
            }
            bar_arrive(BAR_FREE + p, 2 * GRP);          // done reading ring[p]

            bar_sync(BAR_PART2 + q, 2 * GRP);           // part2(t) ready from G2
            const float* ppq = pp + q * S_PER_BLK * G_DIM;
            #pragma unroll
            for (int s = 0; s < S_PER_BLK; s++) {
                const float vA = preA[s] + ppq[s * G_DIM + rA];
                ga1[s * G_DIM + rA] = fsig(vA);
                const float vB = preB[s] + ppq[s * G_DIM + rB];
                ga1[s * G_DIM + rB] = tanhB ? ftanh(vB) : fsig(vB);
            }
            bar_sync(BAR_GA1, GRP);                     // ga1 ready within G1

            {
                float iv = ga1[p0s * G_DIM + p0h];
                float fv = ga1[p0s * G_DIM + p0h + H_DIM];
                float gv = ga1[p0s * G_DIM + p0h + 2 * H_DIM];
                float ov = ga1[p0s * G_DIM + p0h + 3 * H_DIM];
                c2r0 = __fmaf_rn(fv, c2r0, iv * gv);
                h2s[q * S_PER_BLK * H_DIM + p0s * H_DIM + p0h] = ov * ftanh(c2r0);

                iv = ga1[p1s * G_DIM + p1h];
                fv = ga1[p1s * G_DIM + p1h + H_DIM];
                gv = ga1[p1s * G_DIM + p1h + 2 * H_DIM];
                ov = ga1[p1s * G_DIM + p1h + 3 * H_DIM];
                c2r1 = __fmaf_rn(fv, c2r1, iv * gv);
                h2s[q * S_PER_BLK * H_DIM + p1s * H_DIM + p1h] = ov * ftanh(c2r1);
            }
            bar_arrive(BAR_H2RDY + q, 2 * GRP);         // publish h2(t) to G2
        }
    } else {
        // ========== G2: shadow. part2 = b1 + h2(t-1) * W_hh1, rows rA,rB ==========
        const int t2 = tid - 2 * GRP;
        const int rA = t2;
        const int rB = t2 + 128;

        float4 w2a[16], w2b[16];
        {
            const float4* pa = (const float4*)(W_hh1 + rA * H_DIM);
            const float4* pb = (const float4*)(W_hh1 + rB * H_DIM);
            #pragma unroll
            for (int i = 0; i < 16; i++) { w2a[i] = pa[i]; w2b[i] = pb[i]; }
        }
        const float biasA = b1[rA];
        const float biasB = b1[rB];

        for (int t = 0; t < T_STEPS; t++) {
            const int q  = t & 1;
            const int qr = (t - 1) & 1;     // h2(t-1) buffer (t=0 -> h2s[1] = zeros)

            bar_sync(BAR_H2RDY + qr, 2 * GRP);          // h2(t-1) ready

            const float4* h2p = (const float4*)(h2s + qr * S_PER_BLK * H_DIM);
            float* ppq = pp + q * S_PER_BLK * G_DIM;
            #pragma unroll
            for (int half = 0; half < 2; half++) {
                const int s0 = 2 * half, s1 = s0 + 1;
                ull aA0 = packf2(biasA, 0.f), aA1 = packf2(biasA, 0.f);
                ull aB0 = packf2(biasB, 0.f), aB1 = packf2(biasB, 0.f);
                #pragma unroll
                for (int k = 0; k < 16; k++) {
                    const float4 hv0 = h2p[s0 * 16 + k];
                    const float4 hv1 = h2p[s1 * 16 + k];
                    fma2(aA0, f4lo(w2a[k]), f4lo(hv0), aA0);
                    fma2(aA0, f4hi(w2a[k]), f4hi(hv0), aA0);
                    fma2(aA1, f4lo(w2a[k]), f4lo(hv1), aA1);
                    fma2(aA1, f4hi(w2a[k]), f4hi(hv1), aA1);
                    fma2(aB0, f4lo(w2b[k]), f4lo(hv0), aB0);
                    fma2(aB0, f4hi(w2b[k]), f4hi(hv0), aB0);
                    fma2(aB1, f4lo(w2b[k]), f4lo(hv1), aB1);
                    fma2(aB1, f4hi(w2b[k]), f4hi(hv1), aB1);
                }
                ppq[s0 * G_DIM + rA] = fold2(aA0);
                ppq[s1 * G_DIM + rA] = fold2(aA1);
                ppq[s0 * G_DIM + rB] = fold2(aB0);
                ppq[s1 * G_DIM + rB] = fold2(aB1);
            }
            bar_arrive(BAR_PART2 + q, 2 * GRP);         // part2(t) published
        }
    }

    __syncthreads();

    // ---------- classifier: h2 final is in h2s[(T-1)&1] = h2s[1] ----------
    const float* h2f = h2s + ((T_STEPS - 1) & 1) * S_PER_BLK * H_DIM;
    if (tid < S_PER_BLK * 32) {
        int s = tid >> 5, j = tid & 31;
        float a = b_fc1[j];
        #pragma unroll
        for (int k = 0; k < H_DIM; k++)
            a = __fmaf_rn(h2f[s * H_DIM + k], W_fc1[j * H_DIM + k], a);
        ga0[s * 32 + j] = fmaxf(a, 0.f);
    }
    __syncthreads();
    if (tid < S_PER_BLK) {
        float a = b_fc2[0];
        #pragma unroll
        for (int j = 0; j < 32; j++)
            a = __fmaf_rn(ga0[tid * 32 + j], W_fc2[j], a);
        out[bb + tid] = fsig(a);
    }
}

extern "C" void kernel_launch(void* const* d_in, const int* in_sizes, int n_in,
                              void* d_out, int out_size)
{
    const float* x     = (const float*)d_in[0];
    const float* W_ih0 = (const float*)d_in[1];
    const float* W_hh0 = (const float*)d_in[2];
    const float* b0    = (const float*)d_in[3];
    const float* W_ih1 = (const float*)d_in[4];
    const float* W_hh1 = (const float*)d_in[5];
    const float* b1    = (const float*)d_in[6];
    const float* W_fc1 = (const float*)d_in[7];
    const float* b_fc1 = (const float*)d_in[8];
    const float* W_fc2 = (const float*)d_in[9];
    const float* b_fc2 = (const float*)d_in[10];
    float* out = (float*)d_out;

    const size_t smem_bytes =
        (size_t)(S_PER_BLK * T_STEPS * D_DIM          // xs
                 + RING_D * S_PER_BLK * H_DIM         // ring
                 + 2 * S_PER_BLK * H_DIM              // h2s (double)
                 + 2 * S_PER_BLK * G_DIM              // ga0, ga1
                 + 2 * S_PER_BLK * G_DIM)             // pp (double)
        * sizeof(float);

    cudaFuncSetAttribute(lstm_fused_kernel,
                         cudaFuncAttributeMaxDynamicSharedMemorySize,
                         (int)smem_bytes);

    const int nblocks = 512 / S_PER_BLK;   // 128
    lstm_fused_kernel<<<nblocks, NTHREADS, smem_bytes>>>(
        x, W_ih0, W_hh0, b0, W_ih1, W_hh1, b1,
        W_fc1, b_fc1, W_fc2, b_fc2, out);
}

// round 12
// speedup vs baseline: 1.4721x; 1.0167x over previous
#include <cuda_runtime.h>

#define S_PER_BLK 4
#define T_STEPS   1024
#define H_DIM     64
#define G_DIM     256   // 4*H
#define D_DIM     4
#define NTHREADS  384   // 3 groups x 128
#define GRP       128
#define RING_D    4

// named barrier ids (0 reserved for __syncthreads)
#define BAR_READY  1   // 1..4  (phase p)  G0 arrive / G1 sync, count 256
#define BAR_FREE   5   // 5..8  (phase p)  G1 arrive / G0 sync, count 256
#define BAR_H2RDY  9   // 9..10 (q)        G1 arrive / G2 sync, count 256
#define BAR_PART2  11  // 11..12 (q)       G2 arrive / G1 sync, count 256

typedef unsigned long long ull;

__device__ __forceinline__ void bar_sync(int id, int cnt) {
    asm volatile("bar.sync %0, %1;" :: "r"(id), "r"(cnt) : "memory");
}
__device__ __forceinline__ void bar_arrive(int id, int cnt) {
    asm volatile("bar.arrive %0, %1;" :: "r"(id), "r"(cnt) : "memory");
}

// ---- fast activations: single-MUFU tanh.approx ----
__device__ __forceinline__ float ftanh(float x) {
    float r;
    asm("tanh.approx.f32 %0, %1;" : "=f"(r) : "f"(x));
    return r;
}
__device__ __forceinline__ float fsig(float x) {
    float r;
    asm("tanh.approx.f32 %0, %1;" : "=f"(r) : "f"(0.5f * x));
    return __fmaf_rn(0.5f, r, 0.5f);
}

// ---- packed f32x2 fma (sm_100+) ----
__device__ __forceinline__ void fma2(ull& d, ull a, ull b, ull c) {
    asm("fma.rn.f32x2 %0, %1, %2, %3;" : "=l"(d) : "l"(a), "l"(b), "l"(c));
}
__device__ __forceinline__ float fold2(ull a) {
    float lo, hi;
    asm("mov.b64 {%0,%1}, %2;" : "=f"(lo), "=f"(hi) : "l"(a));
    return lo + hi;
}
__device__ __forceinline__ ull packf2(float lo, float hi) {
    ull r; asm("mov.b64 %0, {%1,%2};" : "=l"(r) : "f"(lo), "f"(hi)); return r;
}
__device__ __forceinline__ ull f4lo(const float4& v) {
    ull r; asm("mov.b64 %0, {%1,%2};" : "=l"(r) : "f"(v.x), "f"(v.y)); return r;
}
__device__ __forceinline__ ull f4hi(const float4& v) {
    ull r; asm("mov.b64 %0, {%1,%2};" : "=l"(r) : "f"(v.z), "f"(v.w)); return r;
}

// smem layout (floats):
//   xs   : S*T*D      = 16384
//   ring : RING_D*S*H = 1024   (h1 ring, G0 -> G1; classifier scratch after loop)
//   h2s  : 2*S*H      = 512    (h2 double buffer, G1 -> G2)
//   ppA  : 2*GRP*4    = 1024   (part2 rows rA, thread-linear float4, G2 -> G1)
//   ppB  : 2*GRP*4    = 1024   (part2 rows rB)
// total 19968 floats = 79872 bytes

__global__ __launch_bounds__(NTHREADS, 1)
void lstm_fused_kernel(const float* __restrict__ x,
                       const float* __restrict__ W_ih0,
                       const float* __restrict__ W_hh0,
                       const float* __restrict__ b0,
                       const float* __restrict__ W_ih1,
                       const float* __restrict__ W_hh1,
                       const float* __restrict__ b1,
                       const float* __restrict__ W_fc1,
                       const float* __restrict__ b_fc1,
                       const float* __restrict__ W_fc2,
                       const float* __restrict__ b_fc2,
                       float* __restrict__ out)
{
    extern __shared__ float sm[];
    float* xs   = sm;                                   // [S][T][D]
    float* ring = sm + S_PER_BLK * T_STEPS * D_DIM;     // [RING_D][S][H]
    float* h2s  = ring + RING_D * S_PER_BLK * H_DIM;    // [2][S][H]
    float* ppA  = h2s + 2 * S_PER_BLK * H_DIM;          // [2][GRP][4]
    float* ppB  = ppA + 2 * GRP * 4;                    // [2][GRP][4]

    const int tid = threadIdx.x;
    const int bb  = blockIdx.x * S_PER_BLK;

    // ---- common staging ----
    {
        const float4* gx = (const float4*)(x + (size_t)bb * T_STEPS * D_DIM);
        float4*       sx = (float4*)xs;
        #pragma unroll 4
        for (int i = tid; i < S_PER_BLK * T_STEPS; i += NTHREADS) sx[i] = gx[i];
    }
    for (int i = tid; i < RING_D * S_PER_BLK * H_DIM; i += NTHREADS) ring[i] = 0.f;
    for (int i = tid; i < 2 * S_PER_BLK * H_DIM; i += NTHREADS) h2s[i] = 0.f;

    __syncthreads();

    if (tid < GRP) {
        // ===== G0: layer 0. thread (j = tid>>1, parity = tid&1) =====
        // rows rA = j + parity*64 (i_j or f_j, sigmoid), rB = rA + 128 (g_j tanh / o_j sigmoid)
        const int j      = tid >> 1;
        const int parity = tid & 1;
        const int rA     = j + parity * 64;
        const int rB     = rA + 128;
        // B-row activation: parity0 -> tanh (mul=1,scl=1,add=0); parity1 -> sigmoid
        const float mulB = parity ? 0.5f : 1.0f;
        const float sclB = parity ? 0.5f : 1.0f;
        const float addB = parity ? 0.5f : 0.0f;

        float4 w0a[16], w0b[16];
        {
            const float4* pa = (const float4*)(W_hh0 + rA * H_DIM);
            const float4* pb = (const float4*)(W_hh0 + rB * H_DIM);
            #pragma unroll
            for (int i = 0; i < 16; i++) { w0a[i] = pa[i]; w0b[i] = pb[i]; }
        }
        float wiA[D_DIM], wiB[D_DIM];
        #pragma unroll
        for (int d = 0; d < D_DIM; d++) {
            wiA[d] = W_ih0[rA * D_DIM + d];
            wiB[d] = W_ih0[rB * D_DIM + d];
        }
        const float biasA = b0[rA];
        const float biasB = b0[rB];

        float c1a = 0.f, c1b = 0.f;   // samples 2*parity, 2*parity+1 at h=j

        for (int t = 0; t < T_STEPS; t++) {
            const int p = t & 3;
            bar_sync(BAR_FREE + p, 2 * GRP);     // primed by G1

            const float4* h1p = (const float4*)(ring + ((t - 1) & 3) * S_PER_BLK * H_DIM);

            float actA[S_PER_BLK], actB[S_PER_BLK];
            #pragma unroll
            for (int half = 0; half < 2; half++) {
                const int s0 = 2 * half, s1 = s0 + 1;
                const float4 xv0 = ((const float4*)xs)[s0 * T_STEPS + t];
                const float4 xv1 = ((const float4*)xs)[s1 * T_STEPS + t];

                float iA0 = biasA, iA1 = biasA, iB0 = biasB, iB1 = biasB;
                iA0 = __fmaf_rn(xv0.x, wiA[0], iA0); iA0 = __fmaf_rn(xv0.y, wiA[1], iA0);
                iA0 = __fmaf_rn(xv0.z, wiA[2], iA0); iA0 = __fmaf_rn(xv0.w, wiA[3], iA0);
                iA1 = __fmaf_rn(xv1.x, wiA[0], iA1); iA1 = __fmaf_rn(xv1.y, wiA[1], iA1);
                iA1 = __fmaf_rn(xv1.z, wiA[2], iA1); iA1 = __fmaf_rn(xv1.w, wiA[3], iA1);
                iB0 = __fmaf_rn(xv0.x, wiB[0], iB0); iB0 = __fmaf_rn(xv0.y, wiB[1], iB0);
                iB0 = __fmaf_rn(xv0.z, wiB[2], iB0); iB0 = __fmaf_rn(xv0.w, wiB[3], iB0);
                iB1 = __fmaf_rn(xv1.x, wiB[0], iB1); iB1 = __fmaf_rn(xv1.y, wiB[1], iB1);
                iB1 = __fmaf_rn(xv1.z, wiB[2], iB1); iB1 = __fmaf_rn(xv1.w, wiB[3], iB1);

                ull aA0 = packf2(iA0, 0.f), aA1 = packf2(iA1, 0.f);
                ull aB0 = packf2(iB0, 0.f), aB1 = packf2(iB1, 0.f);
                #pragma unroll
                for (int k = 0; k < 16; k++) {
                    const float4 hv0 = h1p[s0 * 16 + k];
                    const float4 hv1 = h1p[s1 * 16 + k];
                    fma2(aA0, f4lo(w0a[k]), f4lo(hv0), aA0);
                    fma2(aA0, f4hi(w0a[k]), f4hi(hv0), aA0);
                    fma2(aA1, f4lo(w0a[k]), f4lo(hv1), aA1);
                    fma2(aA1, f4hi(w0a[k]), f4hi(hv1), aA1);
                    fma2(aB0, f4lo(w0b[k]), f4lo(hv0), aB0);
                    fma2(aB0, f4hi(w0b[k]), f4hi(hv0), aB0);
                    fma2(aB1, f4lo(w0b[k]), f4lo(hv1), aB1);
                    fma2(aB1, f4hi(w0b[k]), f4hi(hv1), aB1);
                }
                actA[s0] = fsig(fold2(aA0));
                actA[s1] = fsig(fold2(aA1));
                actB[s0] = __fmaf_rn(sclB, ftanh(fold2(aB0) * mulB), addB);
                actB[s1] = __fmaf_rn(sclB, ftanh(fold2(aB1) * mulB), addB);
            }

            // pair exchange: even lane (i,g) <-> odd lane (f,o)
            float rxA[S_PER_BLK], rxB[S_PER_BLK];
            #pragma unroll
            for (int s = 0; s < S_PER_BLK; s++) {
                rxA[s] = __shfl_xor_sync(0xffffffffu, actA[s], 1);
                rxB[s] = __shfl_xor_sync(0xffffffffu, actB[s], 1);
            }

            float* rp = ring + p * S_PER_BLK * H_DIM;
            if (parity == 0) {      // own i,g; rx f,o; update samples 0,1
                c1a = __fmaf_rn(rxA[0], c1a, actA[0] * actB[0]);
                rp[0 * H_DIM + j] = rxB[0] * ftanh(c1a);
                c1b = __fmaf_rn(rxA[1], c1b, actA[1] * actB[1]);
                rp[1 * H_DIM + j] = rxB[1] * ftanh(c1b);
            } else {                // own f,o; rx i,g; update samples 2,3
                c1a = __fmaf_rn(actA[2], c1a, rxA[2] * rxB[2]);
                rp[2 * H_DIM + j] = actB[2] * ftanh(c1a);
                c1b = __fmaf_rn(actA[3], c1b, rxA[3] * rxB[3]);
                rp[3 * H_DIM + j] = actB[3] * ftanh(c1b);
            }
            bar_arrive(BAR_READY + p, 2 * GRP);  // publish h1(t)
        }
    } else if (tid < 2 * GRP) {
        // ===== G1: layer-1 critical path. same (j,parity) row map on W_ih1 =====
        const int t1     = tid - GRP;
        const int j      = t1 >> 1;
        const int parity = t1 & 1;
        const int rA     = j + parity * 64;
        const int rB     = rA + 128;
        const float mulB = parity ? 0.5f : 1.0f;
        const float sclB = parity ? 0.5f : 1.0f;
        const float addB = parity ? 0.5f : 0.0f;

        float4 w1a[16], w1b[16];
        {
            const float4* pa = (const float4*)(W_ih1 + rA * H_DIM);
            const float4* pb = (const float4*)(W_ih1 + rB * H_DIM);
            #pragma unroll
            for (int i = 0; i < 16; i++) { w1a[i] = pa[i]; w1b[i] = pb[i]; }
        }

        float c2a = 0.f, c2b = 0.f;

        // prime: RING_D free slots; h2(-1) "ready" in h2s[1]
        #pragma unroll
        for (int p = 0; p < RING_D; p++) bar_arrive(BAR_FREE + p, 2 * GRP);
        bar_arrive(BAR_H2RDY + 1, 2 * GRP);

        for (int t = 0; t < T_STEPS; t++) {
            const int p = t & 3;
            const int q = t & 1;

            bar_sync(BAR_READY + p, 2 * GRP);    // h1(t) ready

            const float4* h1c = (const float4*)(ring + p * S_PER_BLK * H_DIM);
            float preA[S_PER_BLK], preB[S_PER_BLK];
            #pragma unroll
            for (int half = 0; half < 2; half++) {
                const int s0 = 2 * half, s1 = s0 + 1;
                ull aA0 = 0, aA1 = 0, aB0 = 0, aB1 = 0;
                #pragma unroll
                for (int k = 0; k < 16; k++) {
                    const float4 hv0 = h1c[s0 * 16 + k];
                    const float4 hv1 = h1c[s1 * 16 + k];
                    fma2(aA0, f4lo(w1a[k]), f4lo(hv0), aA0);
                    fma2(aA0, f4hi(w1a[k]), f4hi(hv0), aA0);
                    fma2(aA1, f4lo(w1a[k]), f4lo(hv1), aA1);
                    fma2(aA1, f4hi(w1a[k]), f4hi(hv1), aA1);
                    fma2(aB0, f4lo(w1b[k]), f4lo(hv0), aB0);
                    fma2(aB0, f4hi(w1b[k]), f4hi(hv0), aB0);
                    fma2(aB1, f4lo(w1b[k]), f4lo(hv1), aB1);
                    fma2(aB1, f4hi(w1b[k]), f4hi(hv1), aB1);
                }
                preA[s0] = fold2(aA0); preA[s1] = fold2(aA1);
                preB[s0] = fold2(aB0); preB[s1] = fold2(aB1);
            }
            bar_arrive(BAR_FREE + p, 2 * GRP);   // done reading ring[p]

            bar_sync(BAR_PART2 + q, 2 * GRP);    // part2(t) ready from G2
            const float4 pA4 = ((const float4*)(ppA + q * GRP * 4))[t1];
            const float4 pB4 = ((const float4*)(ppB + q * GRP * 4))[t1];

            float actA[S_PER_BLK], actB[S_PER_BLK];
            actA[0] = fsig(preA[0] + pA4.x);
            actA[1] = fsig(preA[1] + pA4.y);
            actA[2] = fsig(preA[2] + pA4.z);
            actA[3] = fsig(preA[3] + pA4.w);
            actB[0] = __fmaf_rn(sclB, ftanh((preB[0] + pB4.x) * mulB), addB);
            actB[1] = __fmaf_rn(sclB, ftanh((preB[1] + pB4.y) * mulB), addB);
            actB[2] = __fmaf_rn(sclB, ftanh((preB[2] + pB4.z) * mulB), addB);
            actB[3] = __fmaf_rn(sclB, ftanh((preB[3] + pB4.w) * mulB), addB);

            float rxA[S_PER_BLK], rxB[S_PER_BLK];
            #pragma unroll
            for (int s = 0; s < S_PER_BLK; s++) {
                rxA[s] = __shfl_xor_sync(0xffffffffu, actA[s], 1);
                rxB[s] = __shfl_xor_sync(0xffffffffu, actB[s], 1);
            }

            float* hq = h2s + q * S_PER_BLK * H_DIM;
            if (parity == 0) {      // own i,g; rx f,o; update samples 0,1
                c2a = __fmaf_rn(rxA[0], c2a, actA[0] * actB[0]);
                hq[0 * H_DIM + j] = rxB[0] * ftanh(c2a);
                c2b = __fmaf_rn(rxA[1], c2b, actA[1] * actB[1]);
                hq[1 * H_DIM + j] = rxB[1] * ftanh(c2b);
            } else {                // own f,o; rx i,g; update samples 2,3
                c2a = __fmaf_rn(actA[2], c2a, rxA[2] * rxB[2]);
                hq[2 * H_DIM + j] = actB[2] * ftanh(c2a);
                c2b = __fmaf_rn(actA[3], c2b, rxA[3] * rxB[3]);
                hq[3 * H_DIM + j] = actB[3] * ftanh(c2b);
            }
            bar_arrive(BAR_H2RDY + q, 2 * GRP);  // publish h2(t)
        }
    } else {
        // ===== G2: shadow. part2 = b1 + h2(t-1)*W_hh1, same row map =====
        const int t2     = tid - 2 * GRP;
        const int j      = t2 >> 1;
        const int parity = t2 & 1;
        const int rA     = j + parity * 64;
        const int rB     = rA + 128;

        float4 w2a[16], w2b[16];
        {
            const float4* pa = (const float4*)(W_hh1 + rA * H_DIM);
            const float4* pb = (const float4*)(W_hh1 + rB * H_DIM);
            #pragma unroll
            for (int i = 0; i < 16; i++) { w2a[i] = pa[i]; w2b[i] = pb[i]; }
        }
        const float biasA = b1[rA];
        const float biasB = b1[rB];

        for (int t = 0; t < T_STEPS; t++) {
            const int q  = t & 1;
            const int qr = (t - 1) & 1;          // h2(t-1): t=0 -> h2s[1] (zeros)

            bar_sync(BAR_H2RDY + qr, 2 * GRP);   // h2(t-1) ready

            const float4* h2p = (const float4*)(h2s + qr * S_PER_BLK * H_DIM);
            float pA[S_PER_BLK], pB[S_PER_BLK];
            #pragma unroll
            for (int half = 0; half < 2; half++) {
                const int s0 = 2 * half, s1 = s0 + 1;
                ull aA0 = packf2(biasA, 0.f), aA1 = packf2(biasA, 0.f);
                ull aB0 = packf2(biasB, 0.f), aB1 = packf2(biasB, 0.f);
                #pragma unroll
                for (int k = 0; k < 16; k++) {
                    const float4 hv0 = h2p[s0 * 16 + k];
                    const float4 hv1 = h2p[s1 * 16 + k];
                    fma2(aA0, f4lo(w2a[k]), f4lo(hv0), aA0);
                    fma2(aA0, f4hi(w2a[k]), f4hi(hv0), aA0);
                    fma2(aA1, f4lo(w2a[k]), f4lo(hv1), aA1);
                    fma2(aA1, f4hi(w2a[k]), f4hi(hv1), aA1);
                    fma2(aB0, f4lo(w2b[k]), f4lo(hv0), aB0);
                    fma2(aB0, f4hi(w2b[k]), f4hi(hv0), aB0);
                    fma2(aB1, f4lo(w2b[k]), f4lo(hv1), aB1);
                    fma2(aB1, f4hi(w2b[k]), f4hi(hv1), aB1);
                }
                pA[s0] = fold2(aA0); pA[s1] = fold2(aA1);
                pB[s0] = fold2(aB0); pB[s1] = fold2(aB1);
            }
            ((float4*)(ppA + q * GRP * 4))[t2] = make_float4(pA[0], pA[1], pA[2], pA[3]);
            ((float4*)(ppB + q * GRP * 4))[t2] = make_float4(pB[0], pB[1], pB[2], pB[3]);
            bar_arrive(BAR_PART2 + q, 2 * GRP);  // part2(t) published
        }
    }

    __syncthreads();

    // ---------- classifier (ring reused as scratch); h2 final in h2s[1] ----------
    const float* h2f = h2s + ((T_STEPS - 1) & 1) * S_PER_BLK * H_DIM;
    if (tid < S_PER_BLK * 32) {
        int s = tid >> 5, jj = tid & 31;
        float a = b_fc1[jj];
        #pragma unroll
        for (int k = 0; k < H_DIM; k++)
            a = __fmaf_rn(h2f[s * H_DIM + k], W_fc1[jj * H_DIM + k], a);
        ring[s * 32 + jj] = fmaxf(a, 0.f);
    }
    __syncthreads();
    if (tid < S_PER_BLK) {
        float a = b_fc2[0];
        #pragma unroll
        for (int jj = 0; jj < 32; jj++)
            a = __fmaf_rn(ring[tid * 32 + jj], W_fc2[jj], a);
        out[bb + tid] = fsig(a);
    }
}

extern "C" void kernel_launch(void* const* d_in, const int* in_sizes, int n_in,
                              void* d_out, int out_size)
{
    const float* x     = (const float*)d_in[0];
    const float* W_ih0 = (const float*)d_in[1];
    const float* W_hh0 = (const float*)d_in[2];
    const float* b0    = (const float*)d_in[3];
    const float* W_ih1 = (const float*)d_in[4];
    const float* W_hh1 = (const float*)d_in[5];
    const float* b1    = (const float*)d_in[6];
    const float* W_fc1 = (const float*)d_in[7];
    const float* b_fc1 = (const float*)d_in[8];
    const float* W_fc2 = (const float*)d_in[9];
    const float* b_fc2 = (const float*)d_in[10];
    float* out = (float*)d_out;

    const size_t smem_bytes =
        (size_t)(S_PER_BLK * T_STEPS * D_DIM          // xs
                 + RING_D * S_PER_BLK * H_DIM         // ring
                 + 2 * S_PER_BLK * H_DIM              // h2s
                 + 2 * 2 * GRP * 4)                   // ppA, ppB
        * sizeof(float);

    cudaFuncSetAttribute(lstm_fused_kernel,
                         cudaFuncAttributeMaxDynamicSharedMemorySize,
                         (int)smem_bytes);

    const int nblocks = 512 / S_PER_BLK;   // 128
    lstm_fused_kernel<<<nblocks, NTHREADS, smem_bytes>>>(
        x, W_ih0, W_hh0, b0, W_ih1, W_hh1, b1,
        W_fc1, b_fc1, W_fc2, b_fc2, out);
}

// round 13
// speedup vs baseline: 1.5208x; 1.0331x over previous
#include <cuda_runtime.h>
#include <cstdint>

#define S_PER_BLK 4
#define T_STEPS   1024
#define H_DIM     64
#define G_DIM     256   // 4*H
#define D_DIM     4
#define NTHREADS  384   // 3 groups x 128
#define GRP       128
#define RING_D    4
#define H2S_STR   68    // padded h2 row stride (floats) -> conflict-free strided LDS

// named barrier ids (0 reserved for __syncthreads)
#define BAR_READY  1   // 1..4  (phase p)  G0 arrive / G1 sync, count 256
#define BAR_FREE   5   // 5..8  (phase p)  G1 arrive / G0 sync, count 256
#define BAR_H2RDY  9   // 9..10 (q)        G1 arrive / G2 sync, count 256
#define BAR_PART2  11  // 11..12 (q)       G2 arrive / G1 sync, count 256

typedef unsigned long long ull;

__device__ __forceinline__ void bar_sync(int id, int cnt) {
    asm volatile("bar.sync %0, %1;" :: "r"(id), "r"(cnt) : "memory");
}
__device__ __forceinline__ void bar_arrive(int id, int cnt) {
    asm volatile("bar.arrive %0, %1;" :: "r"(id), "r"(cnt) : "memory");
}

// ---- fast activations: single-MUFU tanh.approx ----
__device__ __forceinline__ float ftanh(float x) {
    float r;
    asm("tanh.approx.f32 %0, %1;" : "=f"(r) : "f"(x));
    return r;
}
__device__ __forceinline__ float fsig(float x) {
    float r;
    asm("tanh.approx.f32 %0, %1;" : "=f"(r) : "f"(0.5f * x));
    return __fmaf_rn(0.5f, r, 0.5f);
}

// ---- packed f32x2 fma (sm_100+) ----
__device__ __forceinline__ void fma2(ull& d, ull a, ull b, ull c) {
    asm("fma.rn.f32x2 %0, %1, %2, %3;" : "=l"(d) : "l"(a), "l"(b), "l"(c));
}
__device__ __forceinline__ float fold2(ull a) {
    float lo, hi;
    asm("mov.b64 {%0,%1}, %2;" : "=f"(lo), "=f"(hi) : "l"(a));
    return lo + hi;
}
__device__ __forceinline__ ull packf2(float lo, float hi) {
    ull r; asm("mov.b64 %0, {%1,%2};" : "=l"(r) : "f"(lo), "f"(hi)); return r;
}
__device__ __forceinline__ ull f4lo(const float4& v) {
    ull r; asm("mov.b64 %0, {%1,%2};" : "=l"(r) : "f"(v.x), "f"(v.y)); return r;
}
__device__ __forceinline__ ull f4hi(const float4& v) {
    ull r; asm("mov.b64 %0, {%1,%2};" : "=l"(r) : "f"(v.z), "f"(v.w)); return r;
}

// ---- tf32 warp MMA (sm_80+, retained on sm_100) ----
__device__ __forceinline__ uint32_t cvt_tf32(float f) {
    uint32_t u;
    asm("cvt.rna.tf32.f32 %0, %1;" : "=r"(u) : "f"(f));
    return u;
}
__device__ __forceinline__ void mma_tf32(float& d0, float& d1, float& d2, float& d3,
                                         uint32_t a0, uint32_t a1, uint32_t a2, uint32_t a3,
                                         uint32_t b0, uint32_t b1) {
    asm volatile("mma.sync.aligned.m16n8k8.row.col.f32.tf32.tf32.f32 "
                 "{%0,%1,%2,%3}, {%4,%5,%6,%7}, {%8,%9}, {%0,%1,%2,%3};"
                 : "+f"(d0), "+f"(d1), "+f"(d2), "+f"(d3)
                 : "r"(a0), "r"(a1), "r"(a2), "r"(a3), "r"(b0), "r"(b1));
}

// smem layout (floats):
//   xs   : S*T*D        = 16384
//   ring : RING_D*S*H   = 1024   (h1 ring, G0 -> G1; classifier scratch after loop)
//   h2s  : 2*S*H2S_STR  = 544    (h2 double buffer, padded stride)
//   pp   : 2*256*4      = 2048   (part2, row-indexed [q][row][sample], G2 -> G1)
// total 20000 floats = 80000 bytes

__global__ __launch_bounds__(NTHREADS, 1)
void lstm_fused_kernel(const float* __restrict__ x,
                       const float* __restrict__ W_ih0,
                       const float* __restrict__ W_hh0,
                       const float* __restrict__ b0,
                       const float* __restrict__ W_ih1,
                       const float* __restrict__ W_hh1,
                       const float* __restrict__ b1,
                       const float* __restrict__ W_fc1,
                       const float* __restrict__ b_fc1,
                       const float* __restrict__ W_fc2,
                       const float* __restrict__ b_fc2,
                       float* __restrict__ out)
{
    extern __shared__ float sm[];
    float* xs   = sm;                                   // [S][T][D]
    float* ring = sm + S_PER_BLK * T_STEPS * D_DIM;     // [RING_D][S][H]
    float* h2s  = ring + RING_D * S_PER_BLK * H_DIM;    // [2][S][H2S_STR]
    float* pp   = h2s + 2 * S_PER_BLK * H2S_STR;        // [2][256][4]

    const int tid = threadIdx.x;
    const int bb  = blockIdx.x * S_PER_BLK;

    // ---- common staging ----
    {
        const float4* gx = (const float4*)(x + (size_t)bb * T_STEPS * D_DIM);
        float4*       sx = (float4*)xs;
        #pragma unroll 4
        for (int i = tid; i < S_PER_BLK * T_STEPS; i += NTHREADS) sx[i] = gx[i];
    }
    for (int i = tid; i < RING_D * S_PER_BLK * H_DIM; i += NTHREADS) ring[i] = 0.f;
    for (int i = tid; i < 2 * S_PER_BLK * H2S_STR; i += NTHREADS) h2s[i] = 0.f;

    __syncthreads();

    if (tid < GRP) {
        // ===== G0: layer 0. thread (j = tid>>1, parity = tid&1) — unchanged from R12 =====
        const int j      = tid >> 1;
        const int parity = tid & 1;
        const int rA     = j + parity * 64;
        const int rB     = rA + 128;
        const float mulB = parity ? 0.5f : 1.0f;
        const float sclB = parity ? 0.5f : 1.0f;
        const float addB = parity ? 0.5f : 0.0f;

        float4 w0a[16], w0b[16];
        {
            const float4* pa = (const float4*)(W_hh0 + rA * H_DIM);
            const float4* pb = (const float4*)(W_hh0 + rB * H_DIM);
            #pragma unroll
            for (int i = 0; i < 16; i++) { w0a[i] = pa[i]; w0b[i] = pb[i]; }
        }
        float wiA[D_DIM], wiB[D_DIM];
        #pragma unroll
        for (int d = 0; d < D_DIM; d++) {
            wiA[d] = W_ih0[rA * D_DIM + d];
            wiB[d] = W_ih0[rB * D_DIM + d];
        }
        const float biasA = b0[rA];
        const float biasB = b0[rB];

        float c1a = 0.f, c1b = 0.f;

        for (int t = 0; t < T_STEPS; t++) {
            const int p = t & 3;
            bar_sync(BAR_FREE + p, 2 * GRP);

            const float4* h1p = (const float4*)(ring + ((t - 1) & 3) * S_PER_BLK * H_DIM);

            float actA[S_PER_BLK], actB[S_PER_BLK];
            #pragma unroll
            for (int half = 0; half < 2; half++) {
                const int s0 = 2 * half, s1 = s0 + 1;
                const float4 xv0 = ((const float4*)xs)[s0 * T_STEPS + t];
                const float4 xv1 = ((const float4*)xs)[s1 * T_STEPS + t];

                float iA0 = biasA, iA1 = biasA, iB0 = biasB, iB1 = biasB;
                iA0 = __fmaf_rn(xv0.x, wiA[0], iA0); iA0 = __fmaf_rn(xv0.y, wiA[1], iA0);
                iA0 = __fmaf_rn(xv0.z, wiA[2], iA0); iA0 = __fmaf_rn(xv0.w, wiA[3], iA0);
                iA1 = __fmaf_rn(xv1.x, wiA[0], iA1); iA1 = __fmaf_rn(xv1.y, wiA[1], iA1);
                iA1 = __fmaf_rn(xv1.z, wiA[2], iA1); iA1 = __fmaf_rn(xv1.w, wiA[3], iA1);
                iB0 = __fmaf_rn(xv0.x, wiB[0], iB0); iB0 = __fmaf_rn(xv0.y, wiB[1], iB0);
                iB0 = __fmaf_rn(xv0.z, wiB[2], iB0); iB0 = __fmaf_rn(xv0.w, wiB[3], iB0);
                iB1 = __fmaf_rn(xv1.x, wiB[0], iB1); iB1 = __fmaf_rn(xv1.y, wiB[1], iB1);
                iB1 = __fmaf_rn(xv1.z, wiB[2], iB1); iB1 = __fmaf_rn(xv1.w, wiB[3], iB1);

                ull aA0 = packf2(iA0, 0.f), aA1 = packf2(iA1, 0.f);
                ull aB0 = packf2(iB0, 0.f), aB1 = packf2(iB1, 0.f);
                #pragma unroll
                for (int k = 0; k < 16; k++) {
                    const float4 hv0 = h1p[s0 * 16 + k];
                    const float4 hv1 = h1p[s1 * 16 + k];
                    fma2(aA0, f4lo(w0a[k]), f4lo(hv0), aA0);
                    fma2(aA0, f4hi(w0a[k]), f4hi(hv0), aA0);
                    fma2(aA1, f4lo(w0a[k]), f4lo(hv1), aA1);
                    fma2(aA1, f4hi(w0a[k]), f4hi(hv1), aA1);
                    fma2(aB0, f4lo(w0b[k]), f4lo(hv0), aB0);
                    fma2(aB0, f4hi(w0b[k]), f4hi(hv0), aB0);
                    fma2(aB1, f4lo(w0b[k]), f4lo(hv1), aB1);
                    fma2(aB1, f4hi(w0b[k]), f4hi(hv1), aB1);
                }
                actA[s0] = fsig(fold2(aA0));
                actA[s1] = fsig(fold2(aA1));
                actB[s0] = __fmaf_rn(sclB, ftanh(fold2(aB0) * mulB), addB);
                actB[s1] = __fmaf_rn(sclB, ftanh(fold2(aB1) * mulB), addB);
            }

            float rxA[S_PER_BLK], rxB[S_PER_BLK];
            #pragma unroll
            for (int s = 0; s < S_PER_BLK; s++) {
                rxA[s] = __shfl_xor_sync(0xffffffffu, actA[s], 1);
                rxB[s] = __shfl_xor_sync(0xffffffffu, actB[s], 1);
            }

            float* rp = ring + p * S_PER_BLK * H_DIM;
            if (parity == 0) {
                c1a = __fmaf_rn(rxA[0], c1a, actA[0] * actB[0]);
                rp[0 * H_DIM + j] = rxB[0] * ftanh(c1a);
                c1b = __fmaf_rn(rxA[1], c1b, actA[1] * actB[1]);
                rp[1 * H_DIM + j] = rxB[1] * ftanh(c1b);
            } else {
                c1a = __fmaf_rn(actA[2], c1a, rxA[2] * rxB[2]);
                rp[2 * H_DIM + j] = actB[2] * ftanh(c1a);
                c1b = __fmaf_rn(actA[3], c1b, rxA[3] * rxB[3]);
                rp[3 * H_DIM + j] = actB[3] * ftanh(c1b);
            }
            bar_arrive(BAR_READY + p, 2 * GRP);
        }
    } else if (tid < 2 * GRP) {
        // ===== G1: layer-1 critical path (unchanged from R12 except pp read / h2 stride) =====
        const int t1     = tid - GRP;
        const int j      = t1 >> 1;
        const int parity = t1 & 1;
        const int rA     = j + parity * 64;
        const int rB     = rA + 128;
        const float mulB = parity ? 0.5f : 1.0f;
        const float sclB = parity ? 0.5f : 1.0f;
        const float addB = parity ? 0.5f : 0.0f;

        float4 w1a[16], w1b[16];
        {
            const float4* pa = (const float4*)(W_ih1 + rA * H_DIM);
            const float4* pb = (const float4*)(W_ih1 + rB * H_DIM);
            #pragma unroll
            for (int i = 0; i < 16; i++) { w1a[i] = pa[i]; w1b[i] = pb[i]; }
        }

        float c2a = 0.f, c2b = 0.f;

        #pragma unroll
        for (int p = 0; p < RING_D; p++) bar_arrive(BAR_FREE + p, 2 * GRP);
        bar_arrive(BAR_H2RDY + 1, 2 * GRP);

        for (int t = 0; t < T_STEPS; t++) {
            const int p = t & 3;
            const int q = t & 1;

            bar_sync(BAR_READY + p, 2 * GRP);

            const float4* h1c = (const float4*)(ring + p * S_PER_BLK * H_DIM);
            float preA[S_PER_BLK], preB[S_PER_BLK];
            #pragma unroll
            for (int half = 0; half < 2; half++) {
                const int s0 = 2 * half, s1 = s0 + 1;
                ull aA0 = 0, aA1 = 0, aB0 = 0, aB1 = 0;
                #pragma unroll
                for (int k = 0; k < 16; k++) {
                    const float4 hv0 = h1c[s0 * 16 + k];
                    const float4 hv1 = h1c[s1 * 16 + k];
                    fma2(aA0, f4lo(w1a[k]), f4lo(hv0), aA0);
                    fma2(aA0, f4hi(w1a[k]), f4hi(hv0), aA0);
                    fma2(aA1, f4lo(w1a[k]), f4lo(hv1), aA1);
                    fma2(aA1, f4hi(w1a[k]), f4hi(hv1), aA1);
                    fma2(aB0, f4lo(w1b[k]), f4lo(hv0), aB0);
                    fma2(aB0, f4hi(w1b[k]), f4hi(hv0), aB0);
                    fma2(aB1, f4lo(w1b[k]), f4lo(hv1), aB1);
                    fma2(aB1, f4hi(w1b[k]), f4hi(hv1), aB1);
                }
                preA[s0] = fold2(aA0); preA[s1] = fold2(aA1);
                preB[s0] = fold2(aB0); preB[s1] = fold2(aB1);
            }
            bar_arrive(BAR_FREE + p, 2 * GRP);

            bar_sync(BAR_PART2 + q, 2 * GRP);
            const float4 pA4 = ((const float4*)pp)[q * 256 + rA];
            const float4 pB4 = ((const float4*)pp)[q * 256 + rB];

            float actA[S_PER_BLK], actB[S_PER_BLK];
            actA[0] = fsig(preA[0] + pA4.x);
            actA[1] = fsig(preA[1] + pA4.y);
            actA[2] = fsig(preA[2] + pA4.z);
            actA[3] = fsig(preA[3] + pA4.w);
            actB[0] = __fmaf_rn(sclB, ftanh((preB[0] + pB4.x) * mulB), addB);
            actB[1] = __fmaf_rn(sclB, ftanh((preB[1] + pB4.y) * mulB), addB);
            actB[2] = __fmaf_rn(sclB, ftanh((preB[2] + pB4.z) * mulB), addB);
            actB[3] = __fmaf_rn(sclB, ftanh((preB[3] + pB4.w) * mulB), addB);

            float rxA[S_PER_BLK], rxB[S_PER_BLK];
            #pragma unroll
            for (int s = 0; s < S_PER_BLK; s++) {
                rxA[s] = __shfl_xor_sync(0xffffffffu, actA[s], 1);
                rxB[s] = __shfl_xor_sync(0xffffffffu, actB[s], 1);
            }

            float* hq = h2s + q * S_PER_BLK * H2S_STR;
            if (parity == 0) {
                c2a = __fmaf_rn(rxA[0], c2a, actA[0] * actB[0]);
                hq[0 * H2S_STR + j] = rxB[0] * ftanh(c2a);
                c2b = __fmaf_rn(rxA[1], c2b, actA[1] * actB[1]);
                hq[1 * H2S_STR + j] = rxB[1] * ftanh(c2b);
            } else {
                c2a = __fmaf_rn(actA[2], c2a, rxA[2] * rxB[2]);
                hq[2 * H2S_STR + j] = actB[2] * ftanh(c2a);
                c2b = __fmaf_rn(actA[3], c2b, rxA[3] * rxB[3]);
                hq[3 * H2S_STR + j] = actB[3] * ftanh(c2b);
            }
            bar_arrive(BAR_H2RDY + q, 2 * GRP);
        }
    } else {
        // ===== G2: shadow via tf32 warp MMA. part2 = b1 + h2(t-1) * W_hh1^T =====
        // warp w covers rows [64w, 64w+64) as 4 m16 tiles; K=64 as 8 k8 chunks.
        const int t2   = tid - 2 * GRP;
        const int warp = t2 >> 5;
        const int lane = t2 & 31;
        const int rbase = 64 * warp + (lane >> 2);    // row of a0/a2 within tile 0
        const int kb    = lane & 3;                   // k offset within chunk
        const int s     = (lane >> 2) & 3;            // sample column (cols 4-7 duplicated)

        // A fragments: W_hh1 rows in tf32, resident in 128 regs
        uint32_t A[4][8][4];
        #pragma unroll
        for (int i = 0; i < 4; i++) {
            const float* wr1 = W_hh1 + (rbase + 16 * i) * H_DIM;
            const float* wr2 = wr1 + 8 * H_DIM;
            #pragma unroll
            for (int jj = 0; jj < 8; jj++) {
                const int k = 8 * jj + kb;
                A[i][jj][0] = cvt_tf32(wr1[k]);
                A[i][jj][1] = cvt_tf32(wr2[k]);
                A[i][jj][2] = cvt_tf32(wr1[k + 4]);
                A[i][jj][3] = cvt_tf32(wr2[k + 4]);
            }
        }
        float biasLo[4], biasHi[4];
        #pragma unroll
        for (int i = 0; i < 4; i++) {
            biasLo[i] = b1[rbase + 16 * i];
            biasHi[i] = b1[rbase + 16 * i + 8];
        }

        for (int t = 0; t < T_STEPS; t++) {
            const int q  = t & 1;
            const int qr = (t - 1) & 1;          // h2(t-1): t=0 -> h2s[1] (zeros)

            bar_sync(BAR_H2RDY + qr, 2 * GRP);   // h2(t-1) ready

            const float* h2p = h2s + qr * S_PER_BLK * H2S_STR + s * H2S_STR;
            float d[4][4];
            #pragma unroll
            for (int i = 0; i < 4; i++) {
                d[i][0] = biasLo[i]; d[i][1] = biasLo[i];
                d[i][2] = biasHi[i]; d[i][3] = biasHi[i];
            }
            #pragma unroll
            for (int jj = 0; jj < 8; jj++) {
                const uint32_t b0v = cvt_tf32(h2p[8 * jj + kb]);
                const uint32_t b1v = cvt_tf32(h2p[8 * jj + kb + 4]);
                #pragma unroll
                for (int i = 0; i < 4; i++) {
                    mma_tf32(d[i][0], d[i][1], d[i][2], d[i][3],
                             A[i][jj][0], A[i][jj][1], A[i][jj][2], A[i][jj][3],
                             b0v, b1v);
                }
            }
            // store valid columns (samples 0-3 live in lanes with kb<2)
            if (kb < 2) {
                float* ppq = pp + q * 256 * 4;
                const int sb = 2 * kb;
                #pragma unroll
                for (int i = 0; i < 4; i++) {
                    const int R1 = rbase + 16 * i;
                    *(float2*)(ppq + R1 * 4 + sb)       = make_float2(d[i][0], d[i][1]);
                    *(float2*)(ppq + (R1 + 8) * 4 + sb) = make_float2(d[i][2], d[i][3]);
                }
            }
            bar_arrive(BAR_PART2 + q, 2 * GRP);  // part2(t) published
        }
    }

    __syncthreads();

    // ---------- classifier (ring reused as scratch); h2 final in h2s[1] ----------
    const float* h2f = h2s + ((T_STEPS - 1) & 1) * S_PER_BLK * H2S_STR;
    if (tid < S_PER_BLK * 32) {
        int s = tid >> 5, jj = tid & 31;
        float a = b_fc1[jj];
        #pragma unroll
        for (int k = 0; k < H_DIM; k++)
            a = __fmaf_rn(h2f[s * H2S_STR + k], W_fc1[jj * H_DIM + k], a);
        ring[s * 32 + jj] = fmaxf(a, 0.f);
    }
    __syncthreads();
    if (tid < S_PER_BLK) {
        float a = b_fc2[0];
        #pragma unroll
        for (int jj = 0; jj < 32; jj++)
            a = __fmaf_rn(ring[tid * 32 + jj], W_fc2[jj], a);
        out[bb + tid] = fsig(a);
    }
}

extern "C" void kernel_launch(void* const* d_in, const int* in_sizes, int n_in,
                              void* d_out, int out_size)
{
    const float* x     = (const float*)d_in[0];
    const float* W_ih0 = (const float*)d_in[1];
    const float* W_hh0 = (const float*)d_in[2];
    const float* b0    = (const float*)d_in[3];
    const float* W_ih1 = (const float*)d_in[4];
    const float* W_hh1 = (const float*)d_in[5];
    const float* b1    = (const float*)d_in[6];
    const float* W_fc1 = (const float*)d_in[7];
    const float* b_fc1 = (const float*)d_in[8];
    const float* W_fc2 = (const float*)d_in[9];
    const float* b_fc2 = (const float*)d_in[10];
    float* out = (float*)d_out;

    const size_t smem_bytes =
        (size_t)(S_PER_BLK * T_STEPS * D_DIM          // xs
                 + RING_D * S_PER_BLK * H_DIM         // ring
                 + 2 * S_PER_BLK * H2S_STR            // h2s
                 + 2 * 256 * 4)                       // pp
        * sizeof(float);

    cudaFuncSetAttribute(lstm_fused_kernel,
                         cudaFuncAttributeMaxDynamicSharedMemorySize,
                         (int)smem_bytes);

    const int nblocks = 512 / S_PER_BLK;   // 128
    lstm_fused_kernel<<<nblocks, NTHREADS, smem_bytes>>>(
        x, W_ih0, W_hh0, b0, W_ih1, W_hh1, b1,
        W_fc1, b_fc1, W_fc2, b_fc2, out);
}